// round 8
// baseline (speedup 1.0000x reference)
#include <cuda_runtime.h>

// ---------------- problem constants ----------------
#define DT_F 0.01f
constexpr int N    = 64;     // state dim
constexpr int RNK  = 4;      // low rank
constexpr int DIN  = 128;
constexpr int DOUT = 128;
constexpr int BATCH = 32;
constexpr int T    = 8192;
constexpr int L    = 64;             // chunk length
constexpr int G    = T / L;          // 128 chunks
constexpr int NPOW = 6;              // log2(L)
constexpr int BT   = BATCH * T;      // 262144
constexpr int PF   = 4;              // scan prefetch depth (compile-time ring)

// ---------------- device scratch (static, no allocs) ----------------
__device__ float2 g_bu[(size_t)BT * N];      // 128 MB : B_d @ u  (complex)
__device__ float  g_xr[(size_t)BT * N];      // 64 MB  : Re(x_t)
__device__ float2 g_Bd[DIN * N];             // B_d transposed: [i][n]
__device__ float2 g_Da[N];
__device__ float2 g_U[N * RNK];
__device__ float2 g_V[RNK * N];
__device__ float2 g_Ad[N * N];
__device__ float2 g_Atmp[N * N];
__device__ float2 g_csum[BATCH * G * N];
__device__ float2 g_xin[BATCH * G * N];
__device__ float  g_CT[N * DOUT];            // C transposed: [k][o]
__device__ float  g_DT[DIN * DOUT];          // D transposed: [k][o]
__device__ int    g_dflag;

// ---------------- helpers ----------------
__device__ __forceinline__ float2 cfma(float2 a, float2 b, float2 c) { // c + a*b
    float2 r;
    r.x = fmaf(a.x, b.x, fmaf(-a.y, b.y, c.x));
    r.y = fmaf(a.x, b.y, fmaf( a.y, b.x, c.y));
    return r;
}
__device__ __forceinline__ float2 cmulf(float2 a, float2 b) {
    return cfma(a, b, make_float2(0.f, 0.f));
}
__device__ __forceinline__ unsigned long long ffma2(unsigned long long a,
                                                    unsigned long long b,
                                                    unsigned long long c) {
    unsigned long long d;
    asm("fma.rn.f32x2 %0, %1, %2, %3;" : "=l"(d) : "l"(a), "l"(b), "l"(c));
    return d;
}
__device__ __forceinline__ unsigned long long pack2(float x, float y) {
    unsigned long long r;
    asm("mov.b64 %0, {%1, %2};" : "=l"(r) : "f"(x), "f"(y));
    return r;
}
__device__ __forceinline__ float2 unpack2(unsigned long long v) {
    float x, y;
    asm("mov.b64 {%0, %1}, %2;" : "=f"(x), "=f"(y) : "l"(v));
    return make_float2(x, y);
}
__device__ __forceinline__ unsigned long long dal(double d) {
    return __double_as_longlong(d);
}

// ---------------- setup: Woodbury factors, B_d, dense A_d, transposes, dflag ----------------
__global__ void setup_kernel(const float* __restrict__ lw, const float* __restrict__ zl,
                             const float* __restrict__ P,  const float* __restrict__ Q,
                             const float* __restrict__ Bm, const float* __restrict__ C,
                             const float* __restrict__ D) {
    __shared__ float2 sminv[N];
    __shared__ float2 sS[16];
    __shared__ float2 sK[16];
    __shared__ float2 sW[RNK * DIN];
    __shared__ float  sred[128];
    const float c = 0.5f * DT_F;
    const int t = threadIdx.x;   // 128 threads

    if (t < N) {
        float om = expf(lw[t]);
        float ze = 1.f / (1.f + expf(-zl[t]));
        float lr = -ze * om;
        float li = om * sqrtf(fmaxf(1.f - ze * ze, 1e-8f));
        float mr = 1.f - c * lr;
        float mi = -c * li;
        float inv = 1.f / (mr * mr + mi * mi);
        sminv[t] = make_float2(mr * inv, -mi * inv);
    }
    __syncthreads();

    if (t < 16) {
        int r = t >> 2, s2 = t & 3;
        float2 acc = make_float2(0.f, 0.f);
        for (int k = 0; k < N; k++) {
            float coef = Q[k * RNK + r] * P[k * RNK + s2];
            acc.x += coef * sminv[k].x;
            acc.y += coef * sminv[k].y;
        }
        sS[t] = make_float2(c * acc.x, c * acc.y);
    }
    __syncthreads();

    if (t == 0) {
        float2 M_[4][8];
        for (int i = 0; i < 4; i++)
            for (int j = 0; j < 4; j++) {
                float2 v = sS[i * 4 + j];
                M_[i][j] = make_float2((i == j ? 1.f : 0.f) - v.x, -v.y);
                M_[i][4 + j] = make_float2(i == j ? 1.f : 0.f, 0.f);
            }
        for (int col = 0; col < 4; col++) {
            float2 p = M_[col][col];
            float d = 1.f / (p.x * p.x + p.y * p.y);
            float2 pinv = make_float2(p.x * d, -p.y * d);
            for (int j = 0; j < 8; j++) M_[col][j] = cmulf(M_[col][j], pinv);
            for (int rr = 0; rr < 4; rr++)
                if (rr != col) {
                    float2 f = M_[rr][col];
                    for (int j = 0; j < 8; j++) {
                        float2 s = cmulf(f, M_[col][j]);
                        M_[rr][j].x -= s.x;
                        M_[rr][j].y -= s.y;
                    }
                }
        }
        for (int i = 0; i < 4; i++)
            for (int j = 0; j < 4; j++) sK[i * 4 + j] = M_[i][4 + j];
    }
    __syncthreads();

    if (t < N) {
        float2 mv = sminv[t];
        g_Da[t] = make_float2(2.f * mv.x - 1.f, 2.f * mv.y);
        #pragma unroll
        for (int r = 0; r < RNK; r++) {
            float2 pk = make_float2(0.f, 0.f);
            #pragma unroll
            for (int s2 = 0; s2 < RNK; s2++) {
                float pv = P[t * RNK + s2];
                pk.x += pv * sK[s2 * 4 + r].x;
                pk.y += pv * sK[s2 * 4 + r].y;
            }
            float2 u = cmulf(make_float2(2.f * c * mv.x, 2.f * c * mv.y), pk);
            g_U[t * RNK + r] = u;
            float qv = Q[t * RNK + r];
            g_V[r * N + t] = make_float2(qv * mv.x, qv * mv.y);
        }
    }
    __syncthreads();

    {
        int i = t;
        #pragma unroll
        for (int r = 0; r < RNK; r++) {
            float2 acc = make_float2(0.f, 0.f);
            for (int k = 0; k < N; k++) {
                float coef = Q[k * RNK + r] * Bm[k * DIN + i];
                acc.x += coef * sminv[k].x;
                acc.y += coef * sminv[k].y;
            }
            sW[r * DIN + i] = acc;
        }
    }
    __syncthreads();

    const float sq = sqrtf(DT_F);
    for (int idx = t; idx < N * DIN; idx += 128) {
        int j = idx >> 7, i = idx & 127;
        float2 mv = sminv[j];
        float bv = Bm[j * DIN + i];
        float2 acc = make_float2(bv * mv.x, bv * mv.y);
        #pragma unroll
        for (int r = 0; r < RNK; r++) {
            float2 u = g_U[j * RNK + r];
            acc = cfma(make_float2(0.5f * u.x, 0.5f * u.y), sW[r * DIN + i], acc);
        }
        g_Bd[i * N + j] = make_float2(sq * acc.x, sq * acc.y);
    }
    for (int idx = t; idx < N * N; idx += 128) {
        int j = idx >> 6, k = idx & 63;
        float2 acc = (j == k) ? g_Da[j] : make_float2(0.f, 0.f);
        #pragma unroll
        for (int r = 0; r < RNK; r++) acc = cfma(g_U[j * RNK + r], g_V[r * N + k], acc);
        g_Ad[j * N + k] = acc;
    }
    for (int idx = t; idx < DOUT * N; idx += 128) {
        int o = idx & 127, k = idx >> 7;
        g_CT[k * DOUT + o] = C[o * N + k];
    }
    for (int idx = t; idx < DOUT * DIN; idx += 128) {
        int o = idx & 127, k = idx >> 7;
        g_DT[k * DOUT + o] = D[o * DIN + k];
    }
    {
        float s = 0.f;
        for (int i = t; i < DOUT * DIN; i += 128) s += fabsf(D[i]);
        sred[t] = s;
        __syncthreads();
        for (int st = 64; st > 0; st >>= 1) {
            if (t < st) sred[t] += sred[t + st];
            __syncthreads();
        }
        if (t == 0) g_dflag = (sred[0] != 0.f) ? 1 : 0;
    }
}

// ---------------- A_d^L via NPOW squarings inside ONE cluster kernel ----------------
__global__ void __cluster_dims__(8, 1, 1) __launch_bounds__(128) power_kernel() {
    const int t = threadIdx.x;
    const int cr = blockIdx.x;
    const int row = cr * 8 + (t >> 4);
    const int col = (t & 15) * 4;

    #pragma unroll 1
    for (int it = 0; it < NPOW; it++) {
        const float2* src = (it & 1) ? g_Atmp : g_Ad;
        float2*       dst = (it & 1) ? g_Ad : g_Atmp;
        float2 a0 = make_float2(0.f, 0.f), a1 = a0, a2 = a0, a3 = a0;
        #pragma unroll 8
        for (int k = 0; k < N; k++) {
            float2 av = __ldcg(&src[row * N + k]);
            const float4* bp = (const float4*)&src[k * N + col];
            float4 b01 = __ldcg(&bp[0]);
            float4 b23 = __ldcg(&bp[1]);
            a0 = cfma(av, make_float2(b01.x, b01.y), a0);
            a1 = cfma(av, make_float2(b01.z, b01.w), a1);
            a2 = cfma(av, make_float2(b23.x, b23.y), a2);
            a3 = cfma(av, make_float2(b23.z, b23.w), a3);
        }
        dst[row * N + col + 0] = a0;
        dst[row * N + col + 1] = a1;
        dst[row * N + col + 2] = a2;
        dst[row * N + col + 3] = a3;
        __threadfence();
        asm volatile("barrier.cluster.arrive.aligned;" ::: "memory");
        asm volatile("barrier.cluster.wait.aligned;" ::: "memory");
    }
}

// ---------------- bu = u @ B_d^T (complex out): zero-MOV conflict-free f32x2 GEMM ----------
// a-operand stored SPLATTED in smem (float2(v,v)) -> LDS.128 yields two ull splats directly.
// b-operand stored fragment-major (sb0/sb1[k][tx]) -> conflict-free LDS.128, ull = f4 halves.
__global__ __launch_bounds__(256) void bu_gemm_kernel(const float* __restrict__ u) {
    __shared__ __align__(16) float2 su2[32][130];  // [k][row], splatted a
    __shared__ float4 sb0[32][16];                 // [k][tx]: complex cols 4tx, 4tx+1
    __shared__ float4 sb1[32][16];                 // [k][tx]: complex cols 4tx+2, 4tx+3
    const int tid = threadIdx.x;
    const int tx = tid & 15, ty = tid >> 4;
    const size_t bt0 = (size_t)blockIdx.x * 128;
    typedef unsigned long long ull;

    ull acc[8][4];
    #pragma unroll
    for (int i = 0; i < 8; i++)
        #pragma unroll
        for (int j = 0; j < 4; j++) acc[i][j] = 0ull;

    for (int k0 = 0; k0 < DIN; k0 += 32) {
        // u tile: 128 rows x 32 k, splatted
        #pragma unroll
        for (int l = 0; l < 4; l++) {
            int idx = tid + l * 256;
            int row = idx >> 3, k4 = idx & 7;
            float4 v = *(const float4*)&u[(bt0 + row) * DIN + k0 + k4 * 4];
            su2[k4 * 4 + 0][row] = make_float2(v.x, v.x);
            su2[k4 * 4 + 1][row] = make_float2(v.y, v.y);
            su2[k4 * 4 + 2][row] = make_float2(v.z, v.z);
            su2[k4 * 4 + 3][row] = make_float2(v.w, v.w);
        }
        // Bd tile: fragment-major
        #pragma unroll
        for (int l = 0; l < 4; l++) {
            int idx = tid + l * 256;
            int nn2 = idx & 31, kk = idx >> 5;     // float4 = complex cols (2nn2, 2nn2+1)
            float4 v = *(const float4*)&g_Bd[(k0 + kk) * N + nn2 * 2];
            if (nn2 & 1) sb1[kk][nn2 >> 1] = v;
            else         sb0[kk][nn2 >> 1] = v;
        }
        __syncthreads();
        #pragma unroll
        for (int k = 0; k < 32; k++) {
            double2 b01 = *(const double2*)&sb0[k][tx];
            double2 b23 = *(const double2*)&sb1[k][tx];
            ull b4[4];
            b4[0] = dal(b01.x); b4[1] = dal(b01.y);
            b4[2] = dal(b23.x); b4[3] = dal(b23.y);
            #pragma unroll
            for (int i2 = 0; i2 < 4; i2++) {
                double2 aa = *(const double2*)&su2[k][ty * 8 + i2 * 2];
                ull a0 = dal(aa.x), a1 = dal(aa.y);
                #pragma unroll
                for (int j = 0; j < 4; j++) {
                    acc[2 * i2 + 0][j] = ffma2(a0, b4[j], acc[2 * i2 + 0][j]);
                    acc[2 * i2 + 1][j] = ffma2(a1, b4[j], acc[2 * i2 + 1][j]);
                }
            }
        }
        __syncthreads();
    }
    #pragma unroll
    for (int i = 0; i < 8; i++) {
        #pragma unroll
        for (int jj = 0; jj < 2; jj++) {
            float2 lo = unpack2(acc[i][2 * jj]);
            float2 hi = unpack2(acc[i][2 * jj + 1]);
            float4 v = make_float4(lo.x, lo.y, hi.x, hi.y);
            *(float4*)&g_bu[(bt0 + ty * 8 + i) * N + tx * 4 + 2 * jj] = v;
        }
    }
}

// ---------------- chunked scan, f32x2-packed + shfl butterfly reductions ----------------
__global__ __launch_bounds__(128) void scan_kernel(int mode) {
    const int w  = blockIdx.x * 4 + (threadIdx.x >> 5);
    const int ln = threadIdx.x & 31;
    const int b = w >> 7;        // / G (G=128)
    const int g = w & 127;       // % G
    const size_t bt0 = (size_t)b * T + (size_t)g * L;
    typedef unsigned long long ull;

    float2 Da0 = g_Da[ln], Da1 = g_Da[ln + 32];
    ull da_r  = pack2(Da0.x, Da1.x);
    ull da_i  = pack2(Da0.y, Da1.y);
    ull da_iN = pack2(-Da0.y, -Da1.y);
    ull ur[RNK], ui[RNK], uiN[RNK], vr[RNK], vi[RNK], viN[RNK];
    #pragma unroll
    for (int r = 0; r < RNK; r++) {
        float2 U0 = g_U[ln * RNK + r], U1 = g_U[(ln + 32) * RNK + r];
        float2 V0 = g_V[r * N + ln],   V1 = g_V[r * N + ln + 32];
        ur[r]  = pack2(U0.x, U1.x);
        ui[r]  = pack2(U0.y, U1.y);
        uiN[r] = pack2(-U0.y, -U1.y);
        vr[r]  = pack2(V0.x, V1.x);
        vi[r]  = pack2(V0.y, V1.y);
        viN[r] = pack2(-V0.y, -V1.y);
    }

    ull xr = 0ull, xi = 0ull;
    if (mode) {
        int ci = (b * G + g) * N;
        float2 x0 = g_xin[ci + ln], x1 = g_xin[ci + ln + 32];
        xr = pack2(x0.x, x1.x);
        xi = pack2(x0.y, x1.y);
    }

    const float2* bup = g_bu + bt0 * N;
    float2 pb0[PF], pb1[PF];
    #pragma unroll
    for (int j = 0; j < PF; j++) {
        pb0[j] = bup[j * N + ln];
        pb1[j] = bup[j * N + ln + 32];
    }

    const ull zero = 0ull;
    #pragma unroll 1
    for (int t0 = 0; t0 < L; t0 += PF) {
        #pragma unroll
        for (int j = 0; j < PF; j++) {
            const int t = t0 + j;
            float2 c0 = pb0[j], c1 = pb1[j];
            if (t + PF < L) {
                pb0[j] = bup[(t + PF) * N + ln];
                pb1[j] = bup[(t + PF) * N + ln + 32];
            }
            float sre[RNK], sim[RNK];
            #pragma unroll
            for (int r = 0; r < RNK; r++) {
                ull pr = ffma2(viN[r], xi, ffma2(vr[r], xr, zero));
                ull pi = ffma2(vi[r],  xr, ffma2(vr[r], xi, zero));
                float2 a  = unpack2(pr);
                float2 bb = unpack2(pi);
                sre[r] = a.x + a.y;
                sim[r] = bb.x + bb.y;
            }
            #pragma unroll
            for (int off = 16; off > 0; off >>= 1) {
                #pragma unroll
                for (int r = 0; r < RNK; r++) {
                    sre[r] += __shfl_xor_sync(0xffffffffu, sre[r], off);
                    sim[r] += __shfl_xor_sync(0xffffffffu, sim[r], off);
                }
            }
            ull bur = pack2(c0.x, c1.x);
            ull bui = pack2(c0.y, c1.y);
            ull yr = ffma2(da_r, xr, ffma2(da_iN, xi, bur));
            ull yi = ffma2(da_r, xi, ffma2(da_i,  xr, bui));
            #pragma unroll
            for (int r = 0; r < RNK; r++) {
                ull pr = pack2(sre[r], sre[r]);
                ull pi = pack2(sim[r], sim[r]);
                yr = ffma2(uiN[r], pi, ffma2(ur[r], pr, yr));
                yi = ffma2(ui[r],  pr, ffma2(ur[r], pi, yi));
            }
            xr = yr;
            xi = yi;
            if (mode) {
                float2 o = unpack2(xr);
                g_xr[(bt0 + t) * N + ln]      = o.x;
                g_xr[(bt0 + t) * N + ln + 32] = o.y;
            }
        }
    }
    if (!mode) {
        int ci = (b * G + g) * N;
        float2 rr = unpack2(xr), i2 = unpack2(xi);
        g_csum[ci + ln]      = make_float2(rr.x, i2.x);
        g_csum[ci + ln + 32] = make_float2(rr.y, i2.y);
    }
}

// ---------------- chunk-level chain: x_in[g+1] = A^L x_in[g] + c_g ----------------
__global__ __launch_bounds__(64) void chain_kernel() {
    __shared__ float2 sA[N * 65];
    __shared__ float2 sx[N];
    const int b = blockIdx.x, t = threadIdx.x;
    for (int i = t; i < N * N; i += 64) {
        int r = i >> 6, c = i & 63;
        sA[r * 65 + c] = g_Ad[i];   // A^64
    }
    float2 x = make_float2(0.f, 0.f);
    for (int g = 0; g < G; g++) {
        int ci = (b * G + g) * N;
        g_xin[ci + t] = x;
        sx[t] = x;
        __syncthreads();
        float2 a0 = g_csum[ci + t];
        float2 a1 = make_float2(0.f, 0.f), a2 = a1, a3 = a1;
        #pragma unroll 4
        for (int k = 0; k < N; k += 4) {
            a0 = cfma(sA[t * 65 + k + 0], sx[k + 0], a0);
            a1 = cfma(sA[t * 65 + k + 1], sx[k + 1], a1);
            a2 = cfma(sA[t * 65 + k + 2], sx[k + 2], a2);
            a3 = cfma(sA[t * 65 + k + 3], sx[k + 3], a3);
        }
        x.x = (a0.x + a1.x) + (a2.x + a3.x);
        x.y = (a0.y + a1.y) + (a2.y + a3.y);
        __syncthreads();
    }
}

// ---------------- y = Re(x) @ C^T (+ u @ D^T if D != 0): zero-MOV f32x2 GEMM ---------------
__global__ __launch_bounds__(256) void y_gemm_kernel(const float* __restrict__ u,
                                                     float* __restrict__ out) {
    __shared__ __align__(16) float2 sx2[32][130];  // [k][row], splatted a
    __shared__ float4 sc0[32][16];                 // [k][tx]: cols 8tx .. 8tx+3
    __shared__ float4 sc1[32][16];                 // [k][tx]: cols 8tx+4 .. 8tx+7
    const int tid = threadIdx.x;
    const int tx = tid & 15, ty = tid >> 4;
    const size_t bt0 = (size_t)blockIdx.x * 128;
    typedef unsigned long long ull;

    ull acc[8][4];
    #pragma unroll
    for (int i = 0; i < 8; i++)
        #pragma unroll
        for (int j = 0; j < 4; j++) acc[i][j] = 0ull;

    for (int k0 = 0; k0 < N; k0 += 32) {
        #pragma unroll
        for (int l = 0; l < 4; l++) {
            int idx = tid + l * 256;
            int row = idx >> 3, k4 = idx & 7;
            float4 v = *(const float4*)&g_xr[(bt0 + row) * N + k0 + k4 * 4];
            sx2[k4 * 4 + 0][row] = make_float2(v.x, v.x);
            sx2[k4 * 4 + 1][row] = make_float2(v.y, v.y);
            sx2[k4 * 4 + 2][row] = make_float2(v.z, v.z);
            sx2[k4 * 4 + 3][row] = make_float2(v.w, v.w);
        }
        #pragma unroll
        for (int l = 0; l < 4; l++) {
            int idx = tid + l * 256;
            int o4 = idx & 31, kk = idx >> 5;      // float4 = cols 4*o4 .. 4*o4+3
            float4 v = *(const float4*)&g_CT[(k0 + kk) * DOUT + o4 * 4];
            if (o4 & 1) sc1[kk][o4 >> 1] = v;
            else        sc0[kk][o4 >> 1] = v;
        }
        __syncthreads();
        #pragma unroll
        for (int k = 0; k < 32; k++) {
            double2 c01 = *(const double2*)&sc0[k][tx];
            double2 c23 = *(const double2*)&sc1[k][tx];
            ull b4[4];
            b4[0] = dal(c01.x); b4[1] = dal(c01.y);
            b4[2] = dal(c23.x); b4[3] = dal(c23.y);
            #pragma unroll
            for (int i2 = 0; i2 < 4; i2++) {
                double2 aa = *(const double2*)&sx2[k][ty * 8 + i2 * 2];
                ull a0 = dal(aa.x), a1 = dal(aa.y);
                #pragma unroll
                for (int j = 0; j < 4; j++) {
                    acc[2 * i2 + 0][j] = ffma2(a0, b4[j], acc[2 * i2 + 0][j]);
                    acc[2 * i2 + 1][j] = ffma2(a1, b4[j], acc[2 * i2 + 1][j]);
                }
            }
        }
        __syncthreads();
    }
    if (g_dflag) {
        for (int k0 = 0; k0 < DIN; k0 += 32) {
            #pragma unroll
            for (int l = 0; l < 4; l++) {
                int idx = tid + l * 256;
                int row = idx >> 3, k4 = idx & 7;
                float4 v = *(const float4*)&u[(bt0 + row) * DIN + k0 + k4 * 4];
                sx2[k4 * 4 + 0][row] = make_float2(v.x, v.x);
                sx2[k4 * 4 + 1][row] = make_float2(v.y, v.y);
                sx2[k4 * 4 + 2][row] = make_float2(v.z, v.z);
                sx2[k4 * 4 + 3][row] = make_float2(v.w, v.w);
            }
            #pragma unroll
            for (int l = 0; l < 4; l++) {
                int idx = tid + l * 256;
                int o4 = idx & 31, kk = idx >> 5;
                float4 v = *(const float4*)&g_DT[(k0 + kk) * DOUT + o4 * 4];
                if (o4 & 1) sc1[kk][o4 >> 1] = v;
                else        sc0[kk][o4 >> 1] = v;
            }
            __syncthreads();
            #pragma unroll
            for (int k = 0; k < 32; k++) {
                double2 c01 = *(const double2*)&sc0[k][tx];
                double2 c23 = *(const double2*)&sc1[k][tx];
                ull b4[4];
                b4[0] = dal(c01.x); b4[1] = dal(c01.y);
                b4[2] = dal(c23.x); b4[3] = dal(c23.y);
                #pragma unroll
                for (int i2 = 0; i2 < 4; i2++) {
                    double2 aa = *(const double2*)&sx2[k][ty * 8 + i2 * 2];
                    ull a0 = dal(aa.x), a1 = dal(aa.y);
                    #pragma unroll
                    for (int j = 0; j < 4; j++) {
                        acc[2 * i2 + 0][j] = ffma2(a0, b4[j], acc[2 * i2 + 0][j]);
                        acc[2 * i2 + 1][j] = ffma2(a1, b4[j], acc[2 * i2 + 1][j]);
                    }
                }
            }
            __syncthreads();
        }
    }
    #pragma unroll
    for (int i = 0; i < 8; i++) {
        float2 p0 = unpack2(acc[i][0]);
        float2 p1 = unpack2(acc[i][1]);
        float2 p2 = unpack2(acc[i][2]);
        float2 p3 = unpack2(acc[i][3]);
        float4 v0 = make_float4(p0.x, p0.y, p1.x, p1.y);
        float4 v1 = make_float4(p2.x, p2.y, p3.x, p3.y);
        size_t base = (bt0 + ty * 8 + i) * DOUT + tx * 8;
        *(float4*)&out[base]     = v0;
        *(float4*)&out[base + 4] = v1;
    }
}

// ---------------- launch ----------------
extern "C" void kernel_launch(void* const* d_in, const int* in_sizes, int n_in,
                              void* d_out, int out_size) {
    const float* u  = (const float*)d_in[0];
    const float* lw = (const float*)d_in[1];
    const float* zl = (const float*)d_in[2];
    const float* P  = (const float*)d_in[3];
    const float* Q  = (const float*)d_in[4];
    const float* Bm = (const float*)d_in[5];
    const float* C  = (const float*)d_in[6];
    const float* D  = (const float*)d_in[7];
    float* out = (float*)d_out;

    setup_kernel<<<1, 128>>>(lw, zl, P, Q, Bm, C, D);
    power_kernel<<<8, 128>>>();                 // A_d^64 -> g_Ad
    bu_gemm_kernel<<<BT / 128, 256>>>(u);
    scan_kernel<<<(BATCH * G) / 4, 128>>>(0);   // local chunk sums
    chain_kernel<<<BATCH, 64>>>();              // chunk-level recurrence
    scan_kernel<<<(BATCH * G) / 4, 128>>>(1);   // final pass, store Re(x)
    y_gemm_kernel<<<BT / 128, 256>>>(u, out);
}

// round 10
// speedup vs baseline: 1.0080x; 1.0080x over previous
#include <cuda_runtime.h>

// ---------------- problem constants ----------------
#define DT_F 0.01f
constexpr int N    = 64;     // state dim
constexpr int RNK  = 4;      // low rank
constexpr int DIN  = 128;
constexpr int DOUT = 128;
constexpr int BATCH = 32;
constexpr int T    = 8192;
constexpr int L    = 64;             // chunk length
constexpr int G    = T / L;          // 128 chunks
constexpr int BT   = BATCH * T;      // 262144
constexpr int PF   = 4;              // scan prefetch depth (compile-time ring)

// ---------------- device scratch (static, no allocs) ----------------
__device__ float2 g_bu[(size_t)BT * N];      // 128 MB : B_d @ u  (complex)
__device__ float  g_xr[(size_t)BT * N];      // 64 MB  : Re(x_t)
__device__ float2 g_Bd[DIN * N];             // B_d transposed: [i][n]
__device__ float2 g_Da[N];
__device__ float2 g_U[N * RNK];
__device__ float2 g_V[RNK * N];
__device__ float2 g_Ad[N * N];
__device__ float2 g_Atmp[N * N];
__device__ float2 g_csum[BATCH * G * N];
__device__ float2 g_xin[BATCH * G * N];
__device__ float  g_CT[N * DOUT];            // C transposed: [k][o]
__device__ float  g_DT[DIN * DOUT];          // D transposed: [k][o]
__device__ int    g_dflag;

// ---------------- helpers ----------------
__device__ __forceinline__ float2 cfma(float2 a, float2 b, float2 c) { // c + a*b
    float2 r;
    r.x = fmaf(a.x, b.x, fmaf(-a.y, b.y, c.x));
    r.y = fmaf(a.x, b.y, fmaf( a.y, b.x, c.y));
    return r;
}
__device__ __forceinline__ float2 cmulf(float2 a, float2 b) {
    return cfma(a, b, make_float2(0.f, 0.f));
}
__device__ __forceinline__ unsigned long long ffma2(unsigned long long a,
                                                    unsigned long long b,
                                                    unsigned long long c) {
    unsigned long long d;
    asm("fma.rn.f32x2 %0, %1, %2, %3;" : "=l"(d) : "l"(a), "l"(b), "l"(c));
    return d;
}
__device__ __forceinline__ unsigned long long pack2(float x, float y) {
    unsigned long long r;
    asm("mov.b64 %0, {%1, %2};" : "=l"(r) : "f"(x), "f"(y));
    return r;
}
__device__ __forceinline__ float2 unpack2(unsigned long long v) {
    float x, y;
    asm("mov.b64 {%0, %1}, %2;" : "=f"(x), "=f"(y) : "l"(v));
    return make_float2(x, y);
}

// ---------------- setup: Woodbury factors, B_d, dense A_d, transposes ----------------
__global__ void setup_kernel(const float* __restrict__ lw, const float* __restrict__ zl,
                             const float* __restrict__ P,  const float* __restrict__ Q,
                             const float* __restrict__ Bm, const float* __restrict__ C,
                             const float* __restrict__ D) {
    __shared__ float2 sminv[N];
    __shared__ float2 sS[16];
    __shared__ float2 sK[16];
    __shared__ float2 sW[RNK * DIN];
    const float c = 0.5f * DT_F;
    const int t = threadIdx.x;   // 128 threads

    if (t < N) {
        float om = expf(lw[t]);
        float ze = 1.f / (1.f + expf(-zl[t]));
        float lr = -ze * om;
        float li = om * sqrtf(fmaxf(1.f - ze * ze, 1e-8f));
        float mr = 1.f - c * lr;
        float mi = -c * li;
        float inv = 1.f / (mr * mr + mi * mi);
        sminv[t] = make_float2(mr * inv, -mi * inv);
    }
    __syncthreads();

    // S = c * Q^T Minv P  (4x4 complex)
    if (t < 16) {
        int r = t >> 2, s2 = t & 3;
        float2 acc = make_float2(0.f, 0.f);
        for (int k = 0; k < N; k++) {
            float coef = Q[k * RNK + r] * P[k * RNK + s2];
            acc.x += coef * sminv[k].x;
            acc.y += coef * sminv[k].y;
        }
        sS[t] = make_float2(c * acc.x, c * acc.y);
    }
    __syncthreads();

    // K = inv(I4 - S), Gauss-Jordan
    if (t == 0) {
        float2 M_[4][8];
        for (int i = 0; i < 4; i++)
            for (int j = 0; j < 4; j++) {
                float2 v = sS[i * 4 + j];
                M_[i][j] = make_float2((i == j ? 1.f : 0.f) - v.x, -v.y);
                M_[i][4 + j] = make_float2(i == j ? 1.f : 0.f, 0.f);
            }
        for (int col = 0; col < 4; col++) {
            float2 p = M_[col][col];
            float d = 1.f / (p.x * p.x + p.y * p.y);
            float2 pinv = make_float2(p.x * d, -p.y * d);
            for (int j = 0; j < 8; j++) M_[col][j] = cmulf(M_[col][j], pinv);
            for (int rr = 0; rr < 4; rr++)
                if (rr != col) {
                    float2 f = M_[rr][col];
                    for (int j = 0; j < 8; j++) {
                        float2 s = cmulf(f, M_[col][j]);
                        M_[rr][j].x -= s.x;
                        M_[rr][j].y -= s.y;
                    }
                }
        }
        for (int i = 0; i < 4; i++)
            for (int j = 0; j < 4; j++) sK[i * 4 + j] = M_[i][4 + j];
    }
    __syncthreads();

    // Da, U, V
    if (t < N) {
        float2 mv = sminv[t];
        g_Da[t] = make_float2(2.f * mv.x - 1.f, 2.f * mv.y);
        #pragma unroll
        for (int r = 0; r < RNK; r++) {
            float2 pk = make_float2(0.f, 0.f);
            #pragma unroll
            for (int s2 = 0; s2 < RNK; s2++) {
                float pv = P[t * RNK + s2];
                pk.x += pv * sK[s2 * 4 + r].x;
                pk.y += pv * sK[s2 * 4 + r].y;
            }
            float2 u = cmulf(make_float2(2.f * c * mv.x, 2.f * c * mv.y), pk);
            g_U[t * RNK + r] = u;
            float qv = Q[t * RNK + r];
            g_V[r * N + t] = make_float2(qv * mv.x, qv * mv.y);
        }
    }
    __syncthreads();

    // W[r][i] = sum_k V[r][k] * B[k][i]
    {
        int i = t;
        #pragma unroll
        for (int r = 0; r < RNK; r++) {
            float2 acc = make_float2(0.f, 0.f);
            for (int k = 0; k < N; k++) {
                float coef = Q[k * RNK + r] * Bm[k * DIN + i];
                acc.x += coef * sminv[k].x;
                acc.y += coef * sminv[k].y;
            }
            sW[r * DIN + i] = acc;
        }
    }
    __syncthreads();

    // B_d (transposed store)
    const float sq = sqrtf(DT_F);
    for (int idx = t; idx < N * DIN; idx += 128) {
        int j = idx >> 7, i = idx & 127;
        float2 mv = sminv[j];
        float bv = Bm[j * DIN + i];
        float2 acc = make_float2(bv * mv.x, bv * mv.y);
        #pragma unroll
        for (int r = 0; r < RNK; r++) {
            float2 u = g_U[j * RNK + r];
            acc = cfma(make_float2(0.5f * u.x, 0.5f * u.y), sW[r * DIN + i], acc);
        }
        g_Bd[i * N + j] = make_float2(sq * acc.x, sq * acc.y);
    }
    // dense A_d
    for (int idx = t; idx < N * N; idx += 128) {
        int j = idx >> 6, k = idx & 63;
        float2 acc = (j == k) ? g_Da[j] : make_float2(0.f, 0.f);
        #pragma unroll
        for (int r = 0; r < RNK; r++) acc = cfma(g_U[j * RNK + r], g_V[r * N + k], acc);
        g_Ad[j * N + k] = acc;
    }
    // transposes
    for (int idx = t; idx < DOUT * N; idx += 128) {
        int o = idx & 127, k = idx >> 7;
        g_CT[k * DOUT + o] = C[o * N + k];
    }
    for (int idx = t; idx < DOUT * DIN; idx += 128) {
        int o = idx & 127, k = idx >> 7;
        g_DT[k * DOUT + o] = D[o * DIN + k];
    }
}

// ---------------- D-zero flag ----------------
__global__ void dflag_kernel(const float* __restrict__ D) {
    __shared__ float red[256];
    int tid = threadIdx.x;
    float s = 0.f;
    for (int i = tid; i < DOUT * DIN; i += 256) s += fabsf(D[i]);
    red[tid] = s;
    __syncthreads();
    for (int st = 128; st > 0; st >>= 1) {
        if (tid < st) red[tid] += red[tid + st];
        __syncthreads();
    }
    if (tid == 0) g_dflag = (red[0] != 0.f) ? 1 : 0;
}

// ---------------- A_d^64: 2 squarings per launch, 3 launches ----------------
__global__ void __cluster_dims__(8, 1, 1) __launch_bounds__(128) power_kernel(int it0) {
    const int t = threadIdx.x;
    const int cr = blockIdx.x;
    const int row = cr * 8 + (t >> 4);
    const int col = (t & 15) * 4;

    #pragma unroll 1
    for (int it = it0; it < it0 + 2; it++) {
        const float2* src = (it & 1) ? g_Atmp : g_Ad;
        float2*       dst = (it & 1) ? g_Ad : g_Atmp;
        float2 a0 = make_float2(0.f, 0.f), a1 = a0, a2 = a0, a3 = a0;
        #pragma unroll 8
        for (int k = 0; k < N; k++) {
            float2 av = __ldcg(&src[row * N + k]);
            const float4* bp = (const float4*)&src[k * N + col];
            float4 b01 = __ldcg(&bp[0]);
            float4 b23 = __ldcg(&bp[1]);
            a0 = cfma(av, make_float2(b01.x, b01.y), a0);
            a1 = cfma(av, make_float2(b01.z, b01.w), a1);
            a2 = cfma(av, make_float2(b23.x, b23.y), a2);
            a3 = cfma(av, make_float2(b23.z, b23.w), a3);
        }
        dst[row * N + col + 0] = a0;
        dst[row * N + col + 1] = a1;
        dst[row * N + col + 2] = a2;
        dst[row * N + col + 3] = a3;
        __threadfence();
        asm volatile("barrier.cluster.arrive.aligned;" ::: "memory");
        asm volatile("barrier.cluster.wait.aligned;" ::: "memory");
    }
    // after it=0..5 (3 launches): A_d^64 in g_Ad
}

// ---------------- bu = u @ B_d^T  (complex out), packed f32x2 GEMM (R3-proven) ----------
__global__ __launch_bounds__(256) void bu_gemm_kernel(const float* __restrict__ u) {
    __shared__ float  su[32][129];
    __shared__ float2 sb[32][66];
    const int tid = threadIdx.x;
    const int tx = tid & 15, ty = tid >> 4;
    const size_t bt0 = (size_t)blockIdx.x * 128;

    unsigned long long acc[8][4];
    #pragma unroll
    for (int i = 0; i < 8; i++)
        #pragma unroll
        for (int j = 0; j < 4; j++) acc[i][j] = 0ull;

    for (int k0 = 0; k0 < DIN; k0 += 32) {
        #pragma unroll
        for (int l = 0; l < 4; l++) {
            int idx = tid + l * 256;
            int row = idx >> 3, k4 = idx & 7;
            float4 v = *(const float4*)&u[(bt0 + row) * DIN + k0 + k4 * 4];
            su[k4 * 4 + 0][row] = v.x;
            su[k4 * 4 + 1][row] = v.y;
            su[k4 * 4 + 2][row] = v.z;
            su[k4 * 4 + 3][row] = v.w;
        }
        #pragma unroll
        for (int l = 0; l < 4; l++) {
            int idx = tid + l * 256;
            int nn2 = idx & 31, kk = idx >> 5;
            float4 v = *(const float4*)&g_Bd[(k0 + kk) * N + nn2 * 2];
            *(float4*)&sb[kk][nn2 * 2] = v;
        }
        __syncthreads();
        #pragma unroll
        for (int k = 0; k < 32; k++) {
            unsigned long long a8[8], b4[4];
            #pragma unroll
            for (int i = 0; i < 8; i++) {
                float av = su[k][ty * 8 + i];
                a8[i] = pack2(av, av);
            }
            #pragma unroll
            for (int j = 0; j < 4; j++)
                b4[j] = *(const unsigned long long*)&sb[k][tx * 4 + j];
            #pragma unroll
            for (int i = 0; i < 8; i++)
                #pragma unroll
                for (int j = 0; j < 4; j++) acc[i][j] = ffma2(a8[i], b4[j], acc[i][j]);
        }
        __syncthreads();
    }
    #pragma unroll
    for (int i = 0; i < 8; i++) {
        #pragma unroll
        for (int jj = 0; jj < 2; jj++) {
            float2 lo = unpack2(acc[i][2 * jj]);
            float2 hi = unpack2(acc[i][2 * jj + 1]);
            float4 v = make_float4(lo.x, lo.y, hi.x, hi.y);
            *(float4*)&g_bu[(bt0 + ty * 8 + i) * N + tx * 4 + 2 * jj] = v;
        }
    }
}

// ---------------- chunked scan (R8-proven: packed f32x2 + compile-time ring) -------------
__global__ __launch_bounds__(128) void scan_kernel(int mode) {
    const int w  = blockIdx.x * 4 + (threadIdx.x >> 5);
    const int ln = threadIdx.x & 31;
    const int b = w >> 7;        // / G (G=128)
    const int g = w & 127;       // % G
    const size_t bt0 = (size_t)b * T + (size_t)g * L;
    typedef unsigned long long ull;

    float2 Da0 = g_Da[ln], Da1 = g_Da[ln + 32];
    ull da_r  = pack2(Da0.x, Da1.x);
    ull da_i  = pack2(Da0.y, Da1.y);
    ull da_iN = pack2(-Da0.y, -Da1.y);
    ull ur[RNK], ui[RNK], uiN[RNK], vr[RNK], vi[RNK], viN[RNK];
    #pragma unroll
    for (int r = 0; r < RNK; r++) {
        float2 U0 = g_U[ln * RNK + r], U1 = g_U[(ln + 32) * RNK + r];
        float2 V0 = g_V[r * N + ln],   V1 = g_V[r * N + ln + 32];
        ur[r]  = pack2(U0.x, U1.x);
        ui[r]  = pack2(U0.y, U1.y);
        uiN[r] = pack2(-U0.y, -U1.y);
        vr[r]  = pack2(V0.x, V1.x);
        vi[r]  = pack2(V0.y, V1.y);
        viN[r] = pack2(-V0.y, -V1.y);
    }

    ull xr = 0ull, xi = 0ull;
    if (mode) {
        int ci = (b * G + g) * N;
        float2 x0 = g_xin[ci + ln], x1 = g_xin[ci + ln + 32];
        xr = pack2(x0.x, x1.x);
        xi = pack2(x0.y, x1.y);
    }

    const float2* bup = g_bu + bt0 * N;
    float2 pb0[PF], pb1[PF];
    #pragma unroll
    for (int j = 0; j < PF; j++) {
        pb0[j] = bup[j * N + ln];
        pb1[j] = bup[j * N + ln + 32];
    }

    const ull zero = 0ull;
    #pragma unroll 1
    for (int t0 = 0; t0 < L; t0 += PF) {
        #pragma unroll
        for (int j = 0; j < PF; j++) {
            const int t = t0 + j;
            float2 c0 = pb0[j], c1 = pb1[j];
            if (t + PF < L) {
                pb0[j] = bup[(t + PF) * N + ln];
                pb1[j] = bup[(t + PF) * N + ln + 32];
            }
            float sre[RNK], sim[RNK];
            #pragma unroll
            for (int r = 0; r < RNK; r++) {
                ull pr = ffma2(viN[r], xi, ffma2(vr[r], xr, zero));
                ull pi = ffma2(vi[r],  xr, ffma2(vr[r], xi, zero));
                float2 a  = unpack2(pr);
                float2 bb = unpack2(pi);
                sre[r] = a.x + a.y;
                sim[r] = bb.x + bb.y;
            }
            #pragma unroll
            for (int off = 16; off > 0; off >>= 1) {
                #pragma unroll
                for (int r = 0; r < RNK; r++) {
                    sre[r] += __shfl_xor_sync(0xffffffffu, sre[r], off);
                    sim[r] += __shfl_xor_sync(0xffffffffu, sim[r], off);
                }
            }
            ull bur = pack2(c0.x, c1.x);
            ull bui = pack2(c0.y, c1.y);
            ull yr = ffma2(da_r, xr, ffma2(da_iN, xi, bur));
            ull yi = ffma2(da_r, xi, ffma2(da_i,  xr, bui));
            #pragma unroll
            for (int r = 0; r < RNK; r++) {
                ull pr = pack2(sre[r], sre[r]);
                ull pi = pack2(sim[r], sim[r]);
                yr = ffma2(uiN[r], pi, ffma2(ur[r], pr, yr));
                yi = ffma2(ui[r],  pr, ffma2(ur[r], pi, yi));
            }
            xr = yr;
            xi = yi;
            if (mode) {
                float2 o = unpack2(xr);
                g_xr[(bt0 + t) * N + ln]      = o.x;
                g_xr[(bt0 + t) * N + ln + 32] = o.y;
            }
        }
    }
    if (!mode) {
        int ci = (b * G + g) * N;
        float2 rr = unpack2(xr), i2 = unpack2(xi);
        g_csum[ci + ln]      = make_float2(rr.x, i2.x);
        g_csum[ci + ln + 32] = make_float2(rr.y, i2.y);
    }
}

// ---------------- chunk-level chain: x_in[g+1] = A^L x_in[g] + c_g ----------------
__global__ __launch_bounds__(64) void chain_kernel() {
    __shared__ float2 sA[N * 65];
    __shared__ float2 sx[N];
    const int b = blockIdx.x, t = threadIdx.x;
    for (int i = t; i < N * N; i += 64) {
        int r = i >> 6, c = i & 63;
        sA[r * 65 + c] = g_Ad[i];   // A^64
    }
    float2 x = make_float2(0.f, 0.f);
    for (int g = 0; g < G; g++) {
        int ci = (b * G + g) * N;
        g_xin[ci + t] = x;
        sx[t] = x;
        __syncthreads();
        float2 a0 = g_csum[ci + t];
        float2 a1 = make_float2(0.f, 0.f), a2 = a1, a3 = a1;
        #pragma unroll 4
        for (int k = 0; k < N; k += 4) {
            a0 = cfma(sA[t * 65 + k + 0], sx[k + 0], a0);
            a1 = cfma(sA[t * 65 + k + 1], sx[k + 1], a1);
            a2 = cfma(sA[t * 65 + k + 2], sx[k + 2], a2);
            a3 = cfma(sA[t * 65 + k + 3], sx[k + 3], a3);
        }
        x.x = (a0.x + a1.x) + (a2.x + a3.x);
        x.y = (a0.y + a1.y) + (a2.y + a3.y);
        __syncthreads();
    }
}

// ---------------- y = Re(x) @ C^T (+ u @ D^T if D != 0), packed f32x2 GEMM (R3) ----------
__global__ __launch_bounds__(256) void y_gemm_kernel(const float* __restrict__ u,
                                                     float* __restrict__ out) {
    __shared__ float sx[32][129];
    __shared__ float sc[32][132];
    const int tid = threadIdx.x;
    const int tx = tid & 15, ty = tid >> 4;
    const size_t bt0 = (size_t)blockIdx.x * 128;

    unsigned long long acc[8][4];
    #pragma unroll
    for (int i = 0; i < 8; i++)
        #pragma unroll
        for (int j = 0; j < 4; j++) acc[i][j] = 0ull;

    for (int k0 = 0; k0 < N; k0 += 32) {
        #pragma unroll
        for (int l = 0; l < 4; l++) {
            int idx = tid + l * 256;
            int row = idx >> 3, k4 = idx & 7;
            float4 v = *(const float4*)&g_xr[(bt0 + row) * N + k0 + k4 * 4];
            sx[k4 * 4 + 0][row] = v.x;
            sx[k4 * 4 + 1][row] = v.y;
            sx[k4 * 4 + 2][row] = v.z;
            sx[k4 * 4 + 3][row] = v.w;
        }
        #pragma unroll
        for (int l = 0; l < 4; l++) {
            int idx = tid + l * 256;
            int o4 = idx & 31, kk = idx >> 5;
            float4 v = *(const float4*)&g_CT[(k0 + kk) * DOUT + o4 * 4];
            *(float4*)&sc[kk][o4 * 4] = v;
        }
        __syncthreads();
        #pragma unroll
        for (int k = 0; k < 32; k++) {
            unsigned long long a8[8], b4[4];
            #pragma unroll
            for (int i = 0; i < 8; i++) {
                float av = sx[k][ty * 8 + i];
                a8[i] = pack2(av, av);
            }
            #pragma unroll
            for (int j = 0; j < 4; j++)
                b4[j] = *(const unsigned long long*)&sc[k][tx * 8 + 2 * j];
            #pragma unroll
            for (int i = 0; i < 8; i++)
                #pragma unroll
                for (int j = 0; j < 4; j++) acc[i][j] = ffma2(a8[i], b4[j], acc[i][j]);
        }
        __syncthreads();
    }
    if (g_dflag) {
        for (int k0 = 0; k0 < DIN; k0 += 32) {
            #pragma unroll
            for (int l = 0; l < 4; l++) {
                int idx = tid + l * 256;
                int row = idx >> 3, k4 = idx & 7;
                float4 v = *(const float4*)&u[(bt0 + row) * DIN + k0 + k4 * 4];
                sx[k4 * 4 + 0][row] = v.x;
                sx[k4 * 4 + 1][row] = v.y;
                sx[k4 * 4 + 2][row] = v.z;
                sx[k4 * 4 + 3][row] = v.w;
            }
            #pragma unroll
            for (int l = 0; l < 4; l++) {
                int idx = tid + l * 256;
                int o4 = idx & 31, kk = idx >> 5;
                float4 v = *(const float4*)&g_DT[(k0 + kk) * DOUT + o4 * 4];
                *(float4*)&sc[kk][o4 * 4] = v;
            }
            __syncthreads();
            #pragma unroll
            for (int k = 0; k < 32; k++) {
                unsigned long long a8[8], b4[4];
                #pragma unroll
                for (int i = 0; i < 8; i++) {
                    float av = sx[k][ty * 8 + i];
                    a8[i] = pack2(av, av);
                }
                #pragma unroll
                for (int j = 0; j < 4; j++)
                    b4[j] = *(const unsigned long long*)&sc[k][tx * 8 + 2 * j];
                #pragma unroll
                for (int i = 0; i < 8; i++)
                    #pragma unroll
                    for (int j = 0; j < 4; j++) acc[i][j] = ffma2(a8[i], b4[j], acc[i][j]);
            }
            __syncthreads();
        }
    }
    #pragma unroll
    for (int i = 0; i < 8; i++) {
        float2 p0 = unpack2(acc[i][0]);
        float2 p1 = unpack2(acc[i][1]);
        float2 p2 = unpack2(acc[i][2]);
        float2 p3 = unpack2(acc[i][3]);
        float4 v0 = make_float4(p0.x, p0.y, p1.x, p1.y);
        float4 v1 = make_float4(p2.x, p2.y, p3.x, p3.y);
        size_t base = (bt0 + ty * 8 + i) * DOUT + tx * 8;
        *(float4*)&out[base]     = v0;
        *(float4*)&out[base + 4] = v1;
    }
}

// ---------------- launch (bu_gemm deliberately at index 5 for ncu -s 5 -c 1) -------------
extern "C" void kernel_launch(void* const* d_in, const int* in_sizes, int n_in,
                              void* d_out, int out_size) {
    const float* u  = (const float*)d_in[0];
    const float* lw = (const float*)d_in[1];
    const float* zl = (const float*)d_in[2];
    const float* P  = (const float*)d_in[3];
    const float* Q  = (const float*)d_in[4];
    const float* Bm = (const float*)d_in[5];
    const float* C  = (const float*)d_in[6];
    const float* D  = (const float*)d_in[7];
    float* out = (float*)d_out;

    setup_kernel<<<1, 128>>>(lw, zl, P, Q, Bm, C, D);   // 0
    power_kernel<<<8, 128>>>(0);                        // 1
    power_kernel<<<8, 128>>>(2);                        // 2
    power_kernel<<<8, 128>>>(4);                        // 3  -> A_d^64 in g_Ad
    dflag_kernel<<<1, 256>>>(D);                        // 4
    bu_gemm_kernel<<<BT / 128, 256>>>(u);               // 5  <- ncu-profiled launch
    scan_kernel<<<(BATCH * G) / 4, 128>>>(0);           // 6
    chain_kernel<<<BATCH, 64>>>();                      // 7
    scan_kernel<<<(BATCH * G) / 4, 128>>>(1);           // 8
    y_gemm_kernel<<<BT / 128, 256>>>(u, out);           // 9
}

// round 11
// speedup vs baseline: 1.0939x; 1.0852x over previous
#include <cuda_runtime.h>

// ---------------- problem constants ----------------
#define DT_F 0.01f
constexpr int N    = 64;     // state dim
constexpr int RNK  = 4;      // low rank
constexpr int DIN  = 128;
constexpr int DOUT = 128;
constexpr int BATCH = 32;
constexpr int T    = 8192;
constexpr int L    = 64;             // chunk length
constexpr int G    = T / L;          // 128 chunks
constexpr int BT   = BATCH * T;      // 262144
constexpr int PF   = 4;              // scan prefetch depth (compile-time ring)

// ---------------- device scratch (static, no allocs) ----------------
__device__ float2 g_bu[(size_t)BT * N];      // 128 MB : B_d @ u  (complex)
__device__ float  g_xr[(size_t)BT * N];      // 64 MB  : Re(x_t)
__device__ float2 g_Bd[DIN * N];             // B_d transposed: [i][n]
__device__ float2 g_Da[N];
__device__ float2 g_U[N * RNK];
__device__ float2 g_V[RNK * N];
__device__ float2 g_Ad[N * N];
__device__ float2 g_Atmp[N * N];
__device__ float2 g_csum[BATCH * G * N];
__device__ float2 g_xin[BATCH * G * N];
__device__ float  g_CT[N * DOUT];            // C transposed: [k][o]
__device__ float  g_DT[DIN * DOUT];          // D transposed: [k][o]
__device__ int    g_dflag;

// ---------------- helpers ----------------
__device__ __forceinline__ float2 cfma(float2 a, float2 b, float2 c) { // c + a*b
    float2 r;
    r.x = fmaf(a.x, b.x, fmaf(-a.y, b.y, c.x));
    r.y = fmaf(a.x, b.y, fmaf( a.y, b.x, c.y));
    return r;
}
__device__ __forceinline__ float2 cmulf(float2 a, float2 b) {
    return cfma(a, b, make_float2(0.f, 0.f));
}
__device__ __forceinline__ unsigned long long ffma2(unsigned long long a,
                                                    unsigned long long b,
                                                    unsigned long long c) {
    unsigned long long d;
    asm("fma.rn.f32x2 %0, %1, %2, %3;" : "=l"(d) : "l"(a), "l"(b), "l"(c));
    return d;
}
__device__ __forceinline__ unsigned long long pack2(float x, float y) {
    unsigned long long r;
    asm("mov.b64 %0, {%1, %2};" : "=l"(r) : "f"(x), "f"(y));
    return r;
}
__device__ __forceinline__ float2 unpack2(unsigned long long v) {
    float x, y;
    asm("mov.b64 {%0, %1}, %2;" : "=f"(x), "=f"(y) : "l"(v));
    return make_float2(x, y);
}

// ---------------- setup: Woodbury factors, B_d, dense A_d, transposes, dflag ----------------
__global__ void setup_kernel(const float* __restrict__ lw, const float* __restrict__ zl,
                             const float* __restrict__ P,  const float* __restrict__ Q,
                             const float* __restrict__ Bm, const float* __restrict__ C,
                             const float* __restrict__ D) {
    __shared__ float2 sminv[N];
    __shared__ float2 sS[16];
    __shared__ float2 sK[16];
    __shared__ float2 sW[RNK * DIN];
    __shared__ float  sred[128];
    const float c = 0.5f * DT_F;
    const int t = threadIdx.x;   // 128 threads

    if (t < N) {
        float om = expf(lw[t]);
        float ze = 1.f / (1.f + expf(-zl[t]));
        float lr = -ze * om;
        float li = om * sqrtf(fmaxf(1.f - ze * ze, 1e-8f));
        float mr = 1.f - c * lr;
        float mi = -c * li;
        float inv = 1.f / (mr * mr + mi * mi);
        sminv[t] = make_float2(mr * inv, -mi * inv);
    }
    __syncthreads();

    // S = c * Q^T Minv P  (4x4 complex)
    if (t < 16) {
        int r = t >> 2, s2 = t & 3;
        float2 acc = make_float2(0.f, 0.f);
        for (int k = 0; k < N; k++) {
            float coef = Q[k * RNK + r] * P[k * RNK + s2];
            acc.x += coef * sminv[k].x;
            acc.y += coef * sminv[k].y;
        }
        sS[t] = make_float2(c * acc.x, c * acc.y);
    }
    __syncthreads();

    // K = inv(I4 - S), Gauss-Jordan
    if (t == 0) {
        float2 M_[4][8];
        for (int i = 0; i < 4; i++)
            for (int j = 0; j < 4; j++) {
                float2 v = sS[i * 4 + j];
                M_[i][j] = make_float2((i == j ? 1.f : 0.f) - v.x, -v.y);
                M_[i][4 + j] = make_float2(i == j ? 1.f : 0.f, 0.f);
            }
        for (int col = 0; col < 4; col++) {
            float2 p = M_[col][col];
            float d = 1.f / (p.x * p.x + p.y * p.y);
            float2 pinv = make_float2(p.x * d, -p.y * d);
            for (int j = 0; j < 8; j++) M_[col][j] = cmulf(M_[col][j], pinv);
            for (int rr = 0; rr < 4; rr++)
                if (rr != col) {
                    float2 f = M_[rr][col];
                    for (int j = 0; j < 8; j++) {
                        float2 s = cmulf(f, M_[col][j]);
                        M_[rr][j].x -= s.x;
                        M_[rr][j].y -= s.y;
                    }
                }
        }
        for (int i = 0; i < 4; i++)
            for (int j = 0; j < 4; j++) sK[i * 4 + j] = M_[i][4 + j];
    }
    __syncthreads();

    // Da, U, V
    if (t < N) {
        float2 mv = sminv[t];
        g_Da[t] = make_float2(2.f * mv.x - 1.f, 2.f * mv.y);
        #pragma unroll
        for (int r = 0; r < RNK; r++) {
            float2 pk = make_float2(0.f, 0.f);
            #pragma unroll
            for (int s2 = 0; s2 < RNK; s2++) {
                float pv = P[t * RNK + s2];
                pk.x += pv * sK[s2 * 4 + r].x;
                pk.y += pv * sK[s2 * 4 + r].y;
            }
            float2 u = cmulf(make_float2(2.f * c * mv.x, 2.f * c * mv.y), pk);
            g_U[t * RNK + r] = u;
            float qv = Q[t * RNK + r];
            g_V[r * N + t] = make_float2(qv * mv.x, qv * mv.y);
        }
    }
    __syncthreads();

    // W[r][i] = sum_k V[r][k] * B[k][i]
    {
        int i = t;
        #pragma unroll
        for (int r = 0; r < RNK; r++) {
            float2 acc = make_float2(0.f, 0.f);
            for (int k = 0; k < N; k++) {
                float coef = Q[k * RNK + r] * Bm[k * DIN + i];
                acc.x += coef * sminv[k].x;
                acc.y += coef * sminv[k].y;
            }
            sW[r * DIN + i] = acc;
        }
    }
    __syncthreads();

    // B_d (transposed store)
    const float sq = sqrtf(DT_F);
    for (int idx = t; idx < N * DIN; idx += 128) {
        int j = idx >> 7, i = idx & 127;
        float2 mv = sminv[j];
        float bv = Bm[j * DIN + i];
        float2 acc = make_float2(bv * mv.x, bv * mv.y);
        #pragma unroll
        for (int r = 0; r < RNK; r++) {
            float2 u = g_U[j * RNK + r];
            acc = cfma(make_float2(0.5f * u.x, 0.5f * u.y), sW[r * DIN + i], acc);
        }
        g_Bd[i * N + j] = make_float2(sq * acc.x, sq * acc.y);
    }
    // dense A_d
    for (int idx = t; idx < N * N; idx += 128) {
        int j = idx >> 6, k = idx & 63;
        float2 acc = (j == k) ? g_Da[j] : make_float2(0.f, 0.f);
        #pragma unroll
        for (int r = 0; r < RNK; r++) acc = cfma(g_U[j * RNK + r], g_V[r * N + k], acc);
        g_Ad[j * N + k] = acc;
    }
    // transposes
    for (int idx = t; idx < DOUT * N; idx += 128) {
        int o = idx & 127, k = idx >> 7;
        g_CT[k * DOUT + o] = C[o * N + k];
    }
    for (int idx = t; idx < DOUT * DIN; idx += 128) {
        int o = idx & 127, k = idx >> 7;
        g_DT[k * DOUT + o] = D[o * DIN + k];
    }
    // D-zero flag
    {
        float s = 0.f;
        for (int i = t; i < DOUT * DIN; i += 128) s += fabsf(D[i]);
        sred[t] = s;
        __syncthreads();
        for (int st = 64; st > 0; st >>= 1) {
            if (t < st) sred[t] += sred[t + st];
            __syncthreads();
        }
        if (t == 0) g_dflag = (sred[0] != 0.f) ? 1 : 0;
    }
}

// ---------------- A^2 repeated squaring (64x64 complex) — R3-proven plain version ----------
// iter i: src = (i&1)? Atmp : Ad ; dst = opposite. After 6 launches (i=0..5): A_d^64 in g_Ad.
__global__ void sqmat_kernel(int srcSel) {
    const float2* src = srcSel ? g_Atmp : g_Ad;
    float2*       dst = srcSel ? g_Ad : g_Atmp;
    __shared__ float2 srow[N];
    int row = blockIdx.x, t = threadIdx.x;
    srow[t] = src[row * N + t];
    __syncthreads();
    float2 acc = make_float2(0.f, 0.f);
    for (int k = 0; k < N; k++) acc = cfma(srow[k], src[k * N + t], acc);
    dst[row * N + t] = acc;
}

// ---------------- bu = u @ B_d^T  (complex out), packed f32x2 GEMM (R3-proven) ----------
__global__ __launch_bounds__(256) void bu_gemm_kernel(const float* __restrict__ u) {
    __shared__ float  su[32][129];
    __shared__ float2 sb[32][66];
    const int tid = threadIdx.x;
    const int tx = tid & 15, ty = tid >> 4;
    const size_t bt0 = (size_t)blockIdx.x * 128;

    unsigned long long acc[8][4];
    #pragma unroll
    for (int i = 0; i < 8; i++)
        #pragma unroll
        for (int j = 0; j < 4; j++) acc[i][j] = 0ull;

    for (int k0 = 0; k0 < DIN; k0 += 32) {
        #pragma unroll
        for (int l = 0; l < 4; l++) {
            int idx = tid + l * 256;
            int row = idx >> 3, k4 = idx & 7;
            float4 v = *(const float4*)&u[(bt0 + row) * DIN + k0 + k4 * 4];
            su[k4 * 4 + 0][row] = v.x;
            su[k4 * 4 + 1][row] = v.y;
            su[k4 * 4 + 2][row] = v.z;
            su[k4 * 4 + 3][row] = v.w;
        }
        #pragma unroll
        for (int l = 0; l < 4; l++) {
            int idx = tid + l * 256;
            int nn2 = idx & 31, kk = idx >> 5;
            float4 v = *(const float4*)&g_Bd[(k0 + kk) * N + nn2 * 2];
            *(float4*)&sb[kk][nn2 * 2] = v;
        }
        __syncthreads();
        #pragma unroll
        for (int k = 0; k < 32; k++) {
            unsigned long long a8[8], b4[4];
            #pragma unroll
            for (int i = 0; i < 8; i++) {
                float av = su[k][ty * 8 + i];
                a8[i] = pack2(av, av);
            }
            #pragma unroll
            for (int j = 0; j < 4; j++)
                b4[j] = *(const unsigned long long*)&sb[k][tx * 4 + j];
            #pragma unroll
            for (int i = 0; i < 8; i++)
                #pragma unroll
                for (int j = 0; j < 4; j++) acc[i][j] = ffma2(a8[i], b4[j], acc[i][j]);
        }
        __syncthreads();
    }
    #pragma unroll
    for (int i = 0; i < 8; i++) {
        #pragma unroll
        for (int jj = 0; jj < 2; jj++) {
            float2 lo = unpack2(acc[i][2 * jj]);
            float2 hi = unpack2(acc[i][2 * jj + 1]);
            float4 v = make_float4(lo.x, lo.y, hi.x, hi.y);
            *(float4*)&g_bu[(bt0 + ty * 8 + i) * N + tx * 4 + 2 * jj] = v;
        }
    }
}

// ---------------- chunked scan (R8-proven: packed f32x2 + compile-time ring) -------------
__global__ __launch_bounds__(128) void scan_kernel(int mode) {
    const int w  = blockIdx.x * 4 + (threadIdx.x >> 5);
    const int ln = threadIdx.x & 31;
    const int b = w >> 7;        // / G (G=128)
    const int g = w & 127;       // % G
    const size_t bt0 = (size_t)b * T + (size_t)g * L;
    typedef unsigned long long ull;

    float2 Da0 = g_Da[ln], Da1 = g_Da[ln + 32];
    ull da_r  = pack2(Da0.x, Da1.x);
    ull da_i  = pack2(Da0.y, Da1.y);
    ull da_iN = pack2(-Da0.y, -Da1.y);
    ull ur[RNK], ui[RNK], uiN[RNK], vr[RNK], vi[RNK], viN[RNK];
    #pragma unroll
    for (int r = 0; r < RNK; r++) {
        float2 U0 = g_U[ln * RNK + r], U1 = g_U[(ln + 32) * RNK + r];
        float2 V0 = g_V[r * N + ln],   V1 = g_V[r * N + ln + 32];
        ur[r]  = pack2(U0.x, U1.x);
        ui[r]  = pack2(U0.y, U1.y);
        uiN[r] = pack2(-U0.y, -U1.y);
        vr[r]  = pack2(V0.x, V1.x);
        vi[r]  = pack2(V0.y, V1.y);
        viN[r] = pack2(-V0.y, -V1.y);
    }

    ull xr = 0ull, xi = 0ull;
    if (mode) {
        int ci = (b * G + g) * N;
        float2 x0 = g_xin[ci + ln], x1 = g_xin[ci + ln + 32];
        xr = pack2(x0.x, x1.x);
        xi = pack2(x0.y, x1.y);
    }

    const float2* bup = g_bu + bt0 * N;
    float2 pb0[PF], pb1[PF];
    #pragma unroll
    for (int j = 0; j < PF; j++) {
        pb0[j] = bup[j * N + ln];
        pb1[j] = bup[j * N + ln + 32];
    }

    const ull zero = 0ull;
    #pragma unroll 1
    for (int t0 = 0; t0 < L; t0 += PF) {
        #pragma unroll
        for (int j = 0; j < PF; j++) {
            const int t = t0 + j;
            float2 c0 = pb0[j], c1 = pb1[j];
            if (t + PF < L) {
                pb0[j] = bup[(t + PF) * N + ln];
                pb1[j] = bup[(t + PF) * N + ln + 32];
            }
            float sre[RNK], sim[RNK];
            #pragma unroll
            for (int r = 0; r < RNK; r++) {
                ull pr = ffma2(viN[r], xi, ffma2(vr[r], xr, zero));
                ull pi = ffma2(vi[r],  xr, ffma2(vr[r], xi, zero));
                float2 a  = unpack2(pr);
                float2 bb = unpack2(pi);
                sre[r] = a.x + a.y;
                sim[r] = bb.x + bb.y;
            }
            #pragma unroll
            for (int off = 16; off > 0; off >>= 1) {
                #pragma unroll
                for (int r = 0; r < RNK; r++) {
                    sre[r] += __shfl_xor_sync(0xffffffffu, sre[r], off);
                    sim[r] += __shfl_xor_sync(0xffffffffu, sim[r], off);
                }
            }
            ull bur = pack2(c0.x, c1.x);
            ull bui = pack2(c0.y, c1.y);
            ull yr = ffma2(da_r, xr, ffma2(da_iN, xi, bur));
            ull yi = ffma2(da_r, xi, ffma2(da_i,  xr, bui));
            #pragma unroll
            for (int r = 0; r < RNK; r++) {
                ull pr = pack2(sre[r], sre[r]);
                ull pi = pack2(sim[r], sim[r]);
                yr = ffma2(uiN[r], pi, ffma2(ur[r], pr, yr));
                yi = ffma2(ui[r],  pr, ffma2(ur[r], pi, yi));
            }
            xr = yr;
            xi = yi;
            if (mode) {
                float2 o = unpack2(xr);
                g_xr[(bt0 + t) * N + ln]      = o.x;
                g_xr[(bt0 + t) * N + ln + 32] = o.y;
            }
        }
    }
    if (!mode) {
        int ci = (b * G + g) * N;
        float2 rr = unpack2(xr), i2 = unpack2(xi);
        g_csum[ci + ln]      = make_float2(rr.x, i2.x);
        g_csum[ci + ln + 32] = make_float2(rr.y, i2.y);
    }
}

// ---------------- chunk-level chain: x_in[g+1] = A^L x_in[g] + c_g ----------------
__global__ __launch_bounds__(64) void chain_kernel() {
    __shared__ float2 sA[N * 65];
    __shared__ float2 sx[N];
    const int b = blockIdx.x, t = threadIdx.x;
    for (int i = t; i < N * N; i += 64) {
        int r = i >> 6, c = i & 63;
        sA[r * 65 + c] = g_Ad[i];   // A^64 (6 sqmat launches -> result in g_Ad)
    }
    float2 x = make_float2(0.f, 0.f);
    for (int g = 0; g < G; g++) {
        int ci = (b * G + g) * N;
        g_xin[ci + t] = x;
        sx[t] = x;
        __syncthreads();
        float2 a0 = g_csum[ci + t];
        float2 a1 = make_float2(0.f, 0.f), a2 = a1, a3 = a1;
        #pragma unroll 4
        for (int k = 0; k < N; k += 4) {
            a0 = cfma(sA[t * 65 + k + 0], sx[k + 0], a0);
            a1 = cfma(sA[t * 65 + k + 1], sx[k + 1], a1);
            a2 = cfma(sA[t * 65 + k + 2], sx[k + 2], a2);
            a3 = cfma(sA[t * 65 + k + 3], sx[k + 3], a3);
        }
        x.x = (a0.x + a1.x) + (a2.x + a3.x);
        x.y = (a0.y + a1.y) + (a2.y + a3.y);
        __syncthreads();
    }
}

// ---------------- y = Re(x) @ C^T (+ u @ D^T if D != 0), packed f32x2 GEMM (R3) ----------
__global__ __launch_bounds__(256) void y_gemm_kernel(const float* __restrict__ u,
                                                     float* __restrict__ out) {
    __shared__ float sx[32][129];
    __shared__ float sc[32][132];
    const int tid = threadIdx.x;
    const int tx = tid & 15, ty = tid >> 4;
    const size_t bt0 = (size_t)blockIdx.x * 128;

    unsigned long long acc[8][4];
    #pragma unroll
    for (int i = 0; i < 8; i++)
        #pragma unroll
        for (int j = 0; j < 4; j++) acc[i][j] = 0ull;

    for (int k0 = 0; k0 < N; k0 += 32) {
        #pragma unroll
        for (int l = 0; l < 4; l++) {
            int idx = tid + l * 256;
            int row = idx >> 3, k4 = idx & 7;
            float4 v = *(const float4*)&g_xr[(bt0 + row) * N + k0 + k4 * 4];
            sx[k4 * 4 + 0][row] = v.x;
            sx[k4 * 4 + 1][row] = v.y;
            sx[k4 * 4 + 2][row] = v.z;
            sx[k4 * 4 + 3][row] = v.w;
        }
        #pragma unroll
        for (int l = 0; l < 4; l++) {
            int idx = tid + l * 256;
            int o4 = idx & 31, kk = idx >> 5;
            float4 v = *(const float4*)&g_CT[(k0 + kk) * DOUT + o4 * 4];
            *(float4*)&sc[kk][o4 * 4] = v;
        }
        __syncthreads();
        #pragma unroll
        for (int k = 0; k < 32; k++) {
            unsigned long long a8[8], b4[4];
            #pragma unroll
            for (int i = 0; i < 8; i++) {
                float av = sx[k][ty * 8 + i];
                a8[i] = pack2(av, av);
            }
            #pragma unroll
            for (int j = 0; j < 4; j++)
                b4[j] = *(const unsigned long long*)&sc[k][tx * 8 + 2 * j];
            #pragma unroll
            for (int i = 0; i < 8; i++)
                #pragma unroll
                for (int j = 0; j < 4; j++) acc[i][j] = ffma2(a8[i], b4[j], acc[i][j]);
        }
        __syncthreads();
    }
    if (g_dflag) {
        for (int k0 = 0; k0 < DIN; k0 += 32) {
            #pragma unroll
            for (int l = 0; l < 4; l++) {
                int idx = tid + l * 256;
                int row = idx >> 3, k4 = idx & 7;
                float4 v = *(const float4*)&u[(bt0 + row) * DIN + k0 + k4 * 4];
                sx[k4 * 4 + 0][row] = v.x;
                sx[k4 * 4 + 1][row] = v.y;
                sx[k4 * 4 + 2][row] = v.z;
                sx[k4 * 4 + 3][row] = v.w;
            }
            #pragma unroll
            for (int l = 0; l < 4; l++) {
                int idx = tid + l * 256;
                int o4 = idx & 31, kk = idx >> 5;
                float4 v = *(const float4*)&g_DT[(k0 + kk) * DOUT + o4 * 4];
                *(float4*)&sc[kk][o4 * 4] = v;
            }
            __syncthreads();
            #pragma unroll
            for (int k = 0; k < 32; k++) {
                unsigned long long a8[8], b4[4];
                #pragma unroll
                for (int i = 0; i < 8; i++) {
                    float av = sx[k][ty * 8 + i];
                    a8[i] = pack2(av, av);
                }
                #pragma unroll
                for (int j = 0; j < 4; j++)
                    b4[j] = *(const unsigned long long*)&sc[k][tx * 8 + 2 * j];
                #pragma unroll
                for (int i = 0; i < 8; i++)
                    #pragma unroll
                    for (int j = 0; j < 4; j++) acc[i][j] = ffma2(a8[i], b4[j], acc[i][j]);
            }
            __syncthreads();
        }
    }
    #pragma unroll
    for (int i = 0; i < 8; i++) {
        float2 p0 = unpack2(acc[i][0]);
        float2 p1 = unpack2(acc[i][1]);
        float2 p2 = unpack2(acc[i][2]);
        float2 p3 = unpack2(acc[i][3]);
        float4 v0 = make_float4(p0.x, p0.y, p1.x, p1.y);
        float4 v1 = make_float4(p2.x, p2.y, p3.x, p3.y);
        size_t base = (bt0 + ty * 8 + i) * DOUT + tx * 8;
        *(float4*)&out[base]     = v0;
        *(float4*)&out[base + 4] = v1;
    }
}

// ---------------- launch (bu_gemm at index 5 so ncu -s 5 -c 1 profiles it) ---------------
extern "C" void kernel_launch(void* const* d_in, const int* in_sizes, int n_in,
                              void* d_out, int out_size) {
    const float* u  = (const float*)d_in[0];
    const float* lw = (const float*)d_in[1];
    const float* zl = (const float*)d_in[2];
    const float* P  = (const float*)d_in[3];
    const float* Q  = (const float*)d_in[4];
    const float* Bm = (const float*)d_in[5];
    const float* C  = (const float*)d_in[6];
    const float* D  = (const float*)d_in[7];
    float* out = (float*)d_out;

    setup_kernel<<<1, 128>>>(lw, zl, P, Q, Bm, C, D);   // 0
    sqmat_kernel<<<N, N>>>(0);                          // 1  A^2  -> Atmp
    sqmat_kernel<<<N, N>>>(1);                          // 2  A^4  -> Ad
    sqmat_kernel<<<N, N>>>(0);                          // 3  A^8  -> Atmp
    sqmat_kernel<<<N, N>>>(1);                          // 4  A^16 -> Ad
    bu_gemm_kernel<<<BT / 128, 256>>>(u);               // 5  <- ncu-profiled launch
    sqmat_kernel<<<N, N>>>(0);                          // 6  A^32 -> Atmp
    sqmat_kernel<<<N, N>>>(1);                          // 7  A^64 -> Ad
    scan_kernel<<<(BATCH * G) / 4, 128>>>(0);           // 8
    chain_kernel<<<BATCH, 64>>>();                      // 9
    scan_kernel<<<(BATCH * G) / 4, 128>>>(1);           // 10
    y_gemm_kernel<<<BT / 128, 256>>>(u, out);           // 11
}

// round 12
// speedup vs baseline: 1.2553x; 1.1475x over previous
#include <cuda_runtime.h>

// ---------------- problem constants ----------------
#define DT_F 0.01f
constexpr int N    = 64;     // state dim
constexpr int RNK  = 4;      // low rank
constexpr int DIN  = 128;
constexpr int DOUT = 128;
constexpr int BATCH = 32;
constexpr int T    = 8192;
constexpr int L    = 64;             // chunk length
constexpr int G    = T / L;          // 128 chunks
constexpr int BT   = BATCH * T;      // 262144
constexpr int PF   = 4;              // scan prefetch depth (compile-time ring)

// ---------------- device scratch (static, no allocs) ----------------
__device__ float2 g_bu[(size_t)BT * N];      // 128 MB : B_d @ u  (complex)
__device__ float  g_xr[(size_t)BT * N];      // 64 MB  : Re(x_t)
__device__ float2 g_Bd[DIN * N];             // B_d transposed (kept for reference/debug)
__device__ float2 g_Da[N];
__device__ float2 g_U[N * RNK];
__device__ float2 g_V[RNK * N];
__device__ float2 g_Ad[N * N];
__device__ float2 g_Atmp[N * N];
__device__ float2 g_csum[BATCH * G * N];
__device__ float2 g_xin[BATCH * G * N];
__device__ float  g_CT[N * DOUT];            // C transposed: [k][o]
__device__ float  g_DT[DIN * DOUT];          // D transposed: [k][o]
__device__ float  g_Br[DIN * 64];            // B real transposed: [i][n]
__device__ float  g_Wf[DIN * 8];             // W: [k][2r+c] (re,im interleaved)
__device__ float  g_epi[N * 10];             // per-n epilogue consts: me.re,me.im, ue[4].re/im
__device__ int    g_dflag;

// ---------------- helpers ----------------
__device__ __forceinline__ float2 cfma(float2 a, float2 b, float2 c) { // c + a*b
    float2 r;
    r.x = fmaf(a.x, b.x, fmaf(-a.y, b.y, c.x));
    r.y = fmaf(a.x, b.y, fmaf( a.y, b.x, c.y));
    return r;
}
__device__ __forceinline__ float2 cmulf(float2 a, float2 b) {
    return cfma(a, b, make_float2(0.f, 0.f));
}
__device__ __forceinline__ unsigned long long ffma2(unsigned long long a,
                                                    unsigned long long b,
                                                    unsigned long long c) {
    unsigned long long d;
    asm("fma.rn.f32x2 %0, %1, %2, %3;" : "=l"(d) : "l"(a), "l"(b), "l"(c));
    return d;
}
__device__ __forceinline__ unsigned long long pack2(float x, float y) {
    unsigned long long r;
    asm("mov.b64 %0, {%1, %2};" : "=l"(r) : "f"(x), "f"(y));
    return r;
}
__device__ __forceinline__ float2 unpack2(unsigned long long v) {
    float x, y;
    asm("mov.b64 {%0, %1}, %2;" : "=f"(x), "=f"(y) : "l"(v));
    return make_float2(x, y);
}

// ---------------- setup: Woodbury factors, operands, transposes, dflag ----------------
__global__ void setup_kernel(const float* __restrict__ lw, const float* __restrict__ zl,
                             const float* __restrict__ P,  const float* __restrict__ Q,
                             const float* __restrict__ Bm, const float* __restrict__ C,
                             const float* __restrict__ D) {
    __shared__ float2 sminv[N];
    __shared__ float2 sS[16];
    __shared__ float2 sK[16];
    __shared__ float2 sW[RNK * DIN];
    __shared__ float  sred[128];
    const float c = 0.5f * DT_F;
    const int t = threadIdx.x;   // 128 threads

    if (t < N) {
        float om = expf(lw[t]);
        float ze = 1.f / (1.f + expf(-zl[t]));
        float lr = -ze * om;
        float li = om * sqrtf(fmaxf(1.f - ze * ze, 1e-8f));
        float mr = 1.f - c * lr;
        float mi = -c * li;
        float inv = 1.f / (mr * mr + mi * mi);
        sminv[t] = make_float2(mr * inv, -mi * inv);
    }
    __syncthreads();

    // S = c * Q^T Minv P  (4x4 complex)
    if (t < 16) {
        int r = t >> 2, s2 = t & 3;
        float2 acc = make_float2(0.f, 0.f);
        for (int k = 0; k < N; k++) {
            float coef = Q[k * RNK + r] * P[k * RNK + s2];
            acc.x += coef * sminv[k].x;
            acc.y += coef * sminv[k].y;
        }
        sS[t] = make_float2(c * acc.x, c * acc.y);
    }
    __syncthreads();

    // K = inv(I4 - S), Gauss-Jordan
    if (t == 0) {
        float2 M_[4][8];
        for (int i = 0; i < 4; i++)
            for (int j = 0; j < 4; j++) {
                float2 v = sS[i * 4 + j];
                M_[i][j] = make_float2((i == j ? 1.f : 0.f) - v.x, -v.y);
                M_[i][4 + j] = make_float2(i == j ? 1.f : 0.f, 0.f);
            }
        for (int col = 0; col < 4; col++) {
            float2 p = M_[col][col];
            float d = 1.f / (p.x * p.x + p.y * p.y);
            float2 pinv = make_float2(p.x * d, -p.y * d);
            for (int j = 0; j < 8; j++) M_[col][j] = cmulf(M_[col][j], pinv);
            for (int rr = 0; rr < 4; rr++)
                if (rr != col) {
                    float2 f = M_[rr][col];
                    for (int j = 0; j < 8; j++) {
                        float2 s = cmulf(f, M_[col][j]);
                        M_[rr][j].x -= s.x;
                        M_[rr][j].y -= s.y;
                    }
                }
        }
        for (int i = 0; i < 4; i++)
            for (int j = 0; j < 4; j++) sK[i * 4 + j] = M_[i][4 + j];
    }
    __syncthreads();

    // Da, U, V
    if (t < N) {
        float2 mv = sminv[t];
        g_Da[t] = make_float2(2.f * mv.x - 1.f, 2.f * mv.y);
        #pragma unroll
        for (int r = 0; r < RNK; r++) {
            float2 pk = make_float2(0.f, 0.f);
            #pragma unroll
            for (int s2 = 0; s2 < RNK; s2++) {
                float pv = P[t * RNK + s2];
                pk.x += pv * sK[s2 * 4 + r].x;
                pk.y += pv * sK[s2 * 4 + r].y;
            }
            float2 u = cmulf(make_float2(2.f * c * mv.x, 2.f * c * mv.y), pk);
            g_U[t * RNK + r] = u;
            float qv = Q[t * RNK + r];
            g_V[r * N + t] = make_float2(qv * mv.x, qv * mv.y);
        }
    }
    __syncthreads();

    // W[r][i] = sum_k V[r][k] * B[k][i]
    {
        int i = t;
        #pragma unroll
        for (int r = 0; r < RNK; r++) {
            float2 acc = make_float2(0.f, 0.f);
            for (int k = 0; k < N; k++) {
                float coef = Q[k * RNK + r] * Bm[k * DIN + i];
                acc.x += coef * sminv[k].x;
                acc.y += coef * sminv[k].y;
            }
            sW[r * DIN + i] = acc;
        }
    }
    __syncthreads();

    const float sq = sqrtf(DT_F);
    // g_Wf: [k][2r+c]
    #pragma unroll
    for (int r = 0; r < RNK; r++) {
        g_Wf[t * 8 + 2 * r]     = sW[r * DIN + t].x;
        g_Wf[t * 8 + 2 * r + 1] = sW[r * DIN + t].y;
    }
    // g_Br: [i][n] = B[n][i]
    for (int idx = t; idx < DIN * 64; idx += 128) {
        int i = idx >> 6, n = idx & 63;
        g_Br[i * 64 + n] = Bm[n * DIN + i];
    }
    // g_epi: me = sq*minv, ue_r = 0.5*sq*U
    if (t < N) {
        float2 mv = sminv[t];
        g_epi[t * 10 + 0] = sq * mv.x;
        g_epi[t * 10 + 1] = sq * mv.y;
        #pragma unroll
        for (int r = 0; r < RNK; r++) {
            float2 uu = g_U[t * RNK + r];
            g_epi[t * 10 + 2 + 2 * r]     = 0.5f * sq * uu.x;
            g_epi[t * 10 + 2 + 2 * r + 1] = 0.5f * sq * uu.y;
        }
    }
    // B_d (kept; harmless)
    for (int idx = t; idx < N * DIN; idx += 128) {
        int j = idx >> 7, i = idx & 127;
        float2 mv = sminv[j];
        float bv = Bm[j * DIN + i];
        float2 acc = make_float2(bv * mv.x, bv * mv.y);
        #pragma unroll
        for (int r = 0; r < RNK; r++) {
            float2 u = g_U[j * RNK + r];
            acc = cfma(make_float2(0.5f * u.x, 0.5f * u.y), sW[r * DIN + i], acc);
        }
        g_Bd[i * N + j] = make_float2(sq * acc.x, sq * acc.y);
    }
    // dense A_d
    for (int idx = t; idx < N * N; idx += 128) {
        int j = idx >> 6, k = idx & 63;
        float2 acc = (j == k) ? g_Da[j] : make_float2(0.f, 0.f);
        #pragma unroll
        for (int r = 0; r < RNK; r++) acc = cfma(g_U[j * RNK + r], g_V[r * N + k], acc);
        g_Ad[j * N + k] = acc;
    }
    // transposes
    for (int idx = t; idx < DOUT * N; idx += 128) {
        int o = idx & 127, k = idx >> 7;
        g_CT[k * DOUT + o] = C[o * N + k];
    }
    for (int idx = t; idx < DOUT * DIN; idx += 128) {
        int o = idx & 127, k = idx >> 7;
        g_DT[k * DOUT + o] = D[o * DIN + k];
    }
    // D-zero flag
    {
        float s = 0.f;
        for (int i = t; i < DOUT * DIN; i += 128) s += fabsf(D[i]);
        sred[t] = s;
        __syncthreads();
        for (int st = 64; st > 0; st >>= 1) {
            if (t < st) sred[t] += sred[t + st];
            __syncthreads();
        }
        if (t == 0) g_dflag = (sred[0] != 0.f) ? 1 : 0;
    }
}

// ---------------- A^2 repeated squaring (64x64 complex) — R3-proven plain version ----------
__global__ void sqmat_kernel(int srcSel) {
    const float2* src = srcSel ? g_Atmp : g_Ad;
    float2*       dst = srcSel ? g_Ad : g_Atmp;
    __shared__ float2 srow[N];
    int row = blockIdx.x, t = threadIdx.x;
    srow[t] = src[row * N + t];
    __syncthreads();
    float2 acc = make_float2(0.f, 0.f);
    for (int k = 0; k < N; k++) acc = cfma(srow[k], src[k * N + t], acc);
    dst[row * N + t] = acc;
}

// ---------------- bu: REAL GEMM (u @ B^T, 64 cols) + rank-4 term + complex epilogue -------
// bu[n] = me_n * a_n + sum_r ue[n,r] * s_r   (me = sqrt(dt)*minv, ue = 0.5*sqrt(dt)*U)
__global__ __launch_bounds__(256) void bu_gemm_kernel(const float* __restrict__ u) {
    __shared__ float su[32][129];
    __shared__ float sb[32][68];
    __shared__ float sWf[128][8];
    __shared__ float ss[128][8];
    const int tid = threadIdx.x;
    const int tx = tid & 15, ty = tid >> 4;
    const size_t bt0 = (size_t)blockIdx.x * 128;
    typedef unsigned long long ull;

    // per-thread epilogue constants for cols n0..n0+3
    const int n0 = tx * 4;
    float me[4][2], ue[4][8];
    #pragma unroll
    for (int cc = 0; cc < 4; cc++) {
        const float* e = &g_epi[(n0 + cc) * 10];
        me[cc][0] = e[0];
        me[cc][1] = e[1];
        #pragma unroll
        for (int q = 0; q < 8; q++) ue[cc][q] = e[2 + q];
    }
    // W image (4 KB) once per block
    ((float4*)sWf)[tid] = ((const float4*)g_Wf)[tid];

    const int row2 = ty * 8 + (tx >> 1);   // row this thread computes s for
    const int rr0  = (tx & 1) * 4;         // which 4 of the 8 s-components

    ull acc[8][2];
    #pragma unroll
    for (int i = 0; i < 8; i++) { acc[i][0] = 0ull; acc[i][1] = 0ull; }
    float sacc[4] = {0.f, 0.f, 0.f, 0.f};

    for (int k0 = 0; k0 < DIN; k0 += 32) {
        #pragma unroll
        for (int l = 0; l < 4; l++) {
            int idx = tid + l * 256;
            int row = idx >> 3, k4 = idx & 7;
            float4 v = *(const float4*)&u[(bt0 + row) * DIN + k0 + k4 * 4];
            su[k4 * 4 + 0][row] = v.x;
            su[k4 * 4 + 1][row] = v.y;
            su[k4 * 4 + 2][row] = v.z;
            su[k4 * 4 + 3][row] = v.w;
        }
        #pragma unroll
        for (int l = 0; l < 2; l++) {
            int idx = tid + l * 256;
            int n4 = idx & 15, kk = idx >> 4;
            *(float4*)&sb[kk][n4 * 4] = *(const float4*)&g_Br[(k0 + kk) * 64 + n4 * 4];
        }
        __syncthreads();
        #pragma unroll
        for (int k = 0; k < 32; k++) {
            ull a8[8];
            #pragma unroll
            for (int i = 0; i < 8; i++) {
                float av = su[k][ty * 8 + i];
                a8[i] = pack2(av, av);
            }
            ull b0 = *(const ull*)&sb[k][tx * 4];
            ull b1 = *(const ull*)&sb[k][tx * 4 + 2];
            #pragma unroll
            for (int i = 0; i < 8; i++) {
                acc[i][0] = ffma2(a8[i], b0, acc[i][0]);
                acc[i][1] = ffma2(a8[i], b1, acc[i][1]);
            }
            // rank-4 partials
            float uv = su[k][row2];
            float4 wv = *(const float4*)&sWf[k0 + k][rr0];
            sacc[0] = fmaf(uv, wv.x, sacc[0]);
            sacc[1] = fmaf(uv, wv.y, sacc[1]);
            sacc[2] = fmaf(uv, wv.z, sacc[2]);
            sacc[3] = fmaf(uv, wv.w, sacc[3]);
        }
        __syncthreads();
    }
    // exchange s across the row group
    *(float4*)&ss[row2][rr0] = make_float4(sacc[0], sacc[1], sacc[2], sacc[3]);
    __syncthreads();

    // epilogue: bu[n] = me_n*a_n + sum_r ue_r * s_r (complex)
    #pragma unroll
    for (int i = 0; i < 8; i++) {
        const int row = ty * 8 + i;
        float4 sA = *(const float4*)&ss[row][0];
        float4 sB = *(const float4*)&ss[row][4];
        float s_[8] = {sA.x, sA.y, sA.z, sA.w, sB.x, sB.y, sB.z, sB.w};
        float2 lo = unpack2(acc[i][0]);
        float2 hi = unpack2(acc[i][1]);
        float a[4] = {lo.x, lo.y, hi.x, hi.y};
        float o[8];
        #pragma unroll
        for (int cc = 0; cc < 4; cc++) {
            float re = me[cc][0] * a[cc];
            float im = me[cc][1] * a[cc];
            #pragma unroll
            for (int r = 0; r < 4; r++) {
                float urr = ue[cc][2 * r], uii = ue[cc][2 * r + 1];
                re = fmaf(urr, s_[2 * r], fmaf(-uii, s_[2 * r + 1], re));
                im = fmaf(urr, s_[2 * r + 1], fmaf(uii, s_[2 * r], im));
            }
            o[2 * cc]     = re;
            o[2 * cc + 1] = im;
        }
        float* orow = (float*)&g_bu[(bt0 + row) * N] + tx * 8;
        *(float4*)&orow[0] = make_float4(o[0], o[1], o[2], o[3]);
        *(float4*)&orow[4] = make_float4(o[4], o[5], o[6], o[7]);
    }
}

// ---------------- chunked scan (R8-proven: packed f32x2 + compile-time ring) -------------
__global__ __launch_bounds__(128) void scan_kernel(int mode) {
    const int w  = blockIdx.x * 4 + (threadIdx.x >> 5);
    const int ln = threadIdx.x & 31;
    const int b = w >> 7;        // / G (G=128)
    const int g = w & 127;       // % G
    const size_t bt0 = (size_t)b * T + (size_t)g * L;
    typedef unsigned long long ull;

    float2 Da0 = g_Da[ln], Da1 = g_Da[ln + 32];
    ull da_r  = pack2(Da0.x, Da1.x);
    ull da_i  = pack2(Da0.y, Da1.y);
    ull da_iN = pack2(-Da0.y, -Da1.y);
    ull ur[RNK], ui[RNK], uiN[RNK], vr[RNK], vi[RNK], viN[RNK];
    #pragma unroll
    for (int r = 0; r < RNK; r++) {
        float2 U0 = g_U[ln * RNK + r], U1 = g_U[(ln + 32) * RNK + r];
        float2 V0 = g_V[r * N + ln],   V1 = g_V[r * N + ln + 32];
        ur[r]  = pack2(U0.x, U1.x);
        ui[r]  = pack2(U0.y, U1.y);
        uiN[r] = pack2(-U0.y, -U1.y);
        vr[r]  = pack2(V0.x, V1.x);
        vi[r]  = pack2(V0.y, V1.y);
        viN[r] = pack2(-V0.y, -V1.y);
    }

    ull xr = 0ull, xi = 0ull;
    if (mode) {
        int ci = (b * G + g) * N;
        float2 x0 = g_xin[ci + ln], x1 = g_xin[ci + ln + 32];
        xr = pack2(x0.x, x1.x);
        xi = pack2(x0.y, x1.y);
    }

    const float2* bup = g_bu + bt0 * N;
    float2 pb0[PF], pb1[PF];
    #pragma unroll
    for (int j = 0; j < PF; j++) {
        pb0[j] = bup[j * N + ln];
        pb1[j] = bup[j * N + ln + 32];
    }

    const ull zero = 0ull;
    #pragma unroll 1
    for (int t0 = 0; t0 < L; t0 += PF) {
        #pragma unroll
        for (int j = 0; j < PF; j++) {
            const int t = t0 + j;
            float2 c0 = pb0[j], c1 = pb1[j];
            if (t + PF < L) {
                pb0[j] = bup[(t + PF) * N + ln];
                pb1[j] = bup[(t + PF) * N + ln + 32];
            }
            float sre[RNK], sim[RNK];
            #pragma unroll
            for (int r = 0; r < RNK; r++) {
                ull pr = ffma2(viN[r], xi, ffma2(vr[r], xr, zero));
                ull pi = ffma2(vi[r],  xr, ffma2(vr[r], xi, zero));
                float2 a  = unpack2(pr);
                float2 bb = unpack2(pi);
                sre[r] = a.x + a.y;
                sim[r] = bb.x + bb.y;
            }
            #pragma unroll
            for (int off = 16; off > 0; off >>= 1) {
                #pragma unroll
                for (int r = 0; r < RNK; r++) {
                    sre[r] += __shfl_xor_sync(0xffffffffu, sre[r], off);
                    sim[r] += __shfl_xor_sync(0xffffffffu, sim[r], off);
                }
            }
            ull bur = pack2(c0.x, c1.x);
            ull bui = pack2(c0.y, c1.y);
            ull yr = ffma2(da_r, xr, ffma2(da_iN, xi, bur));
            ull yi = ffma2(da_r, xi, ffma2(da_i,  xr, bui));
            #pragma unroll
            for (int r = 0; r < RNK; r++) {
                ull pr = pack2(sre[r], sre[r]);
                ull pi = pack2(sim[r], sim[r]);
                yr = ffma2(uiN[r], pi, ffma2(ur[r], pr, yr));
                yi = ffma2(ui[r],  pr, ffma2(ur[r], pi, yi));
            }
            xr = yr;
            xi = yi;
            if (mode) {
                float2 o = unpack2(xr);
                g_xr[(bt0 + t) * N + ln]      = o.x;
                g_xr[(bt0 + t) * N + ln + 32] = o.y;
            }
        }
    }
    if (!mode) {
        int ci = (b * G + g) * N;
        float2 rr = unpack2(xr), i2 = unpack2(xi);
        g_csum[ci + ln]      = make_float2(rr.x, i2.x);
        g_csum[ci + ln + 32] = make_float2(rr.y, i2.y);
    }
}

// ---------------- chunk-level chain: x_in[g+1] = A^L x_in[g] + c_g ----------------
__global__ __launch_bounds__(64) void chain_kernel() {
    __shared__ float2 sA[N * 65];
    __shared__ float2 sx[N];
    const int b = blockIdx.x, t = threadIdx.x;
    for (int i = t; i < N * N; i += 64) {
        int r = i >> 6, c = i & 63;
        sA[r * 65 + c] = g_Ad[i];   // A^64 (6 sqmat launches -> result in g_Ad)
    }
    float2 x = make_float2(0.f, 0.f);
    for (int g = 0; g < G; g++) {
        int ci = (b * G + g) * N;
        g_xin[ci + t] = x;
        sx[t] = x;
        __syncthreads();
        float2 a0 = g_csum[ci + t];
        float2 a1 = make_float2(0.f, 0.f), a2 = a1, a3 = a1;
        #pragma unroll 4
        for (int k = 0; k < N; k += 4) {
            a0 = cfma(sA[t * 65 + k + 0], sx[k + 0], a0);
            a1 = cfma(sA[t * 65 + k + 1], sx[k + 1], a1);
            a2 = cfma(sA[t * 65 + k + 2], sx[k + 2], a2);
            a3 = cfma(sA[t * 65 + k + 3], sx[k + 3], a3);
        }
        x.x = (a0.x + a1.x) + (a2.x + a3.x);
        x.y = (a0.y + a1.y) + (a2.y + a3.y);
        __syncthreads();
    }
}

// ---------------- y = Re(x) @ C^T (+ u @ D^T if D != 0), packed f32x2 GEMM (R3) ----------
__global__ __launch_bounds__(256) void y_gemm_kernel(const float* __restrict__ u,
                                                     float* __restrict__ out) {
    __shared__ float sx[32][129];
    __shared__ float sc[32][132];
    const int tid = threadIdx.x;
    const int tx = tid & 15, ty = tid >> 4;
    const size_t bt0 = (size_t)blockIdx.x * 128;

    unsigned long long acc[8][4];
    #pragma unroll
    for (int i = 0; i < 8; i++)
        #pragma unroll
        for (int j = 0; j < 4; j++) acc[i][j] = 0ull;

    for (int k0 = 0; k0 < N; k0 += 32) {
        #pragma unroll
        for (int l = 0; l < 4; l++) {
            int idx = tid + l * 256;
            int row = idx >> 3, k4 = idx & 7;
            float4 v = *(const float4*)&g_xr[(bt0 + row) * N + k0 + k4 * 4];
            sx[k4 * 4 + 0][row] = v.x;
            sx[k4 * 4 + 1][row] = v.y;
            sx[k4 * 4 + 2][row] = v.z;
            sx[k4 * 4 + 3][row] = v.w;
        }
        #pragma unroll
        for (int l = 0; l < 4; l++) {
            int idx = tid + l * 256;
            int o4 = idx & 31, kk = idx >> 5;
            float4 v = *(const float4*)&g_CT[(k0 + kk) * DOUT + o4 * 4];
            *(float4*)&sc[kk][o4 * 4] = v;
        }
        __syncthreads();
        #pragma unroll
        for (int k = 0; k < 32; k++) {
            unsigned long long a8[8], b4[4];
            #pragma unroll
            for (int i = 0; i < 8; i++) {
                float av = sx[k][ty * 8 + i];
                a8[i] = pack2(av, av);
            }
            #pragma unroll
            for (int j = 0; j < 4; j++)
                b4[j] = *(const unsigned long long*)&sc[k][tx * 8 + 2 * j];
            #pragma unroll
            for (int i = 0; i < 8; i++)
                #pragma unroll
                for (int j = 0; j < 4; j++) acc[i][j] = ffma2(a8[i], b4[j], acc[i][j]);
        }
        __syncthreads();
    }
    if (g_dflag) {
        for (int k0 = 0; k0 < DIN; k0 += 32) {
            #pragma unroll
            for (int l = 0; l < 4; l++) {
                int idx = tid + l * 256;
                int row = idx >> 3, k4 = idx & 7;
                float4 v = *(const float4*)&u[(bt0 + row) * DIN + k0 + k4 * 4];
                sx[k4 * 4 + 0][row] = v.x;
                sx[k4 * 4 + 1][row] = v.y;
                sx[k4 * 4 + 2][row] = v.z;
                sx[k4 * 4 + 3][row] = v.w;
            }
            #pragma unroll
            for (int l = 0; l < 4; l++) {
                int idx = tid + l * 256;
                int o4 = idx & 31, kk = idx >> 5;
                float4 v = *(const float4*)&g_DT[(k0 + kk) * DOUT + o4 * 4];
                *(float4*)&sc[kk][o4 * 4] = v;
            }
            __syncthreads();
            #pragma unroll
            for (int k = 0; k < 32; k++) {
                unsigned long long a8[8], b4[4];
                #pragma unroll
                for (int i = 0; i < 8; i++) {
                    float av = sx[k][ty * 8 + i];
                    a8[i] = pack2(av, av);
                }
                #pragma unroll
                for (int j = 0; j < 4; j++)
                    b4[j] = *(const unsigned long long*)&sc[k][tx * 8 + 2 * j];
                #pragma unroll
                for (int i = 0; i < 8; i++)
                    #pragma unroll
                    for (int j = 0; j < 4; j++) acc[i][j] = ffma2(a8[i], b4[j], acc[i][j]);
            }
            __syncthreads();
        }
    }
    #pragma unroll
    for (int i = 0; i < 8; i++) {
        float2 p0 = unpack2(acc[i][0]);
        float2 p1 = unpack2(acc[i][1]);
        float2 p2 = unpack2(acc[i][2]);
        float2 p3 = unpack2(acc[i][3]);
        float4 v0 = make_float4(p0.x, p0.y, p1.x, p1.y);
        float4 v1 = make_float4(p2.x, p2.y, p3.x, p3.y);
        size_t base = (bt0 + ty * 8 + i) * DOUT + tx * 8;
        *(float4*)&out[base]     = v0;
        *(float4*)&out[base + 4] = v1;
    }
}

// ---------------- launch (bu at our index 4: harness hidden launch shifts ncu -s 5 here) --
extern "C" void kernel_launch(void* const* d_in, const int* in_sizes, int n_in,
                              void* d_out, int out_size) {
    const float* u  = (const float*)d_in[0];
    const float* lw = (const float*)d_in[1];
    const float* zl = (const float*)d_in[2];
    const float* P  = (const float*)d_in[3];
    const float* Q  = (const float*)d_in[4];
    const float* Bm = (const float*)d_in[5];
    const float* C  = (const float*)d_in[6];
    const float* D  = (const float*)d_in[7];
    float* out = (float*)d_out;

    setup_kernel<<<1, 128>>>(lw, zl, P, Q, Bm, C, D);   // 0
    sqmat_kernel<<<N, N>>>(0);                          // 1  A^2  -> Atmp
    sqmat_kernel<<<N, N>>>(1);                          // 2  A^4  -> Ad
    sqmat_kernel<<<N, N>>>(0);                          // 3  A^8  -> Atmp
    bu_gemm_kernel<<<BT / 128, 256>>>(u);               // 4  <- ncu-profiled launch
    sqmat_kernel<<<N, N>>>(1);                          // 5  A^16 -> Ad
    sqmat_kernel<<<N, N>>>(0);                          // 6  A^32 -> Atmp
    sqmat_kernel<<<N, N>>>(1);                          // 7  A^64 -> Ad
    scan_kernel<<<(BATCH * G) / 4, 128>>>(0);           // 8
    chain_kernel<<<BATCH, 64>>>();                      // 9
    scan_kernel<<<(BATCH * G) / 4, 128>>>(1);           // 10
    y_gemm_kernel<<<BT / 128, 256>>>(u, out);           // 11
}

// round 13
// speedup vs baseline: 1.3708x; 1.0920x over previous
#include <cuda_runtime.h>

// ---------------- problem constants ----------------
#define DT_F 0.01f
constexpr int N    = 64;     // state dim
constexpr int RNK  = 4;      // low rank
constexpr int DIN  = 128;
constexpr int DOUT = 128;
constexpr int BATCH = 32;
constexpr int T    = 8192;
constexpr int L    = 64;             // chunk length
constexpr int G    = T / L;          // 128 chunks
constexpr int BT   = BATCH * T;      // 262144
constexpr int PF   = 4;              // scan prefetch depth (compile-time ring)

// ---------------- device scratch (static, no allocs) ----------------
__device__ float  g_a[(size_t)BT * 64];      // 64 MB : u @ B^T (real)
__device__ float  g_s[(size_t)BT * 8];       // 8 MB  : 0.05 * (u @ W^T) (4 complex = 8 real)
__device__ float  g_xr[(size_t)BT * N];      // 64 MB : Re(x_t)
__device__ float2 g_Da[N];
__device__ float2 g_U[N * RNK];
__device__ float2 g_V[RNK * N];
__device__ float2 g_Ad[N * N];
__device__ float2 g_Atmp[N * N];
__device__ float2 g_csum[BATCH * G * N];
__device__ float2 g_xin[BATCH * G * N];
__device__ float  g_CT[N * DOUT];            // C transposed: [k][o]
__device__ float  g_DT[DIN * DOUT];          // D transposed: [k][o]
__device__ float  g_Br[DIN * 64];            // B real transposed: [i][n]
__device__ float  g_Wf[DIN * 8];             // W: [k][2r+c] (re,im interleaved)
__device__ float  g_epi[N * 10];             // per-n: me.re, me.im, (unused ue kept)
__device__ int    g_dflag;

// ---------------- helpers ----------------
__device__ __forceinline__ float2 cfma(float2 a, float2 b, float2 c) { // c + a*b
    float2 r;
    r.x = fmaf(a.x, b.x, fmaf(-a.y, b.y, c.x));
    r.y = fmaf(a.x, b.y, fmaf( a.y, b.x, c.y));
    return r;
}
__device__ __forceinline__ float2 cmulf(float2 a, float2 b) {
    return cfma(a, b, make_float2(0.f, 0.f));
}
__device__ __forceinline__ unsigned long long ffma2(unsigned long long a,
                                                    unsigned long long b,
                                                    unsigned long long c) {
    unsigned long long d;
    asm("fma.rn.f32x2 %0, %1, %2, %3;" : "=l"(d) : "l"(a), "l"(b), "l"(c));
    return d;
}
__device__ __forceinline__ unsigned long long pack2(float x, float y) {
    unsigned long long r;
    asm("mov.b64 %0, {%1, %2};" : "=l"(r) : "f"(x), "f"(y));
    return r;
}
__device__ __forceinline__ float2 unpack2(unsigned long long v) {
    float x, y;
    asm("mov.b64 {%0, %1}, %2;" : "=f"(x), "=f"(y) : "l"(v));
    return make_float2(x, y);
}

// ---------------- setup: Woodbury factors, operands, transposes, dflag ----------------
__global__ void setup_kernel(const float* __restrict__ lw, const float* __restrict__ zl,
                             const float* __restrict__ P,  const float* __restrict__ Q,
                             const float* __restrict__ Bm, const float* __restrict__ C,
                             const float* __restrict__ D) {
    __shared__ float2 sminv[N];
    __shared__ float2 sS[16];
    __shared__ float2 sK[16];
    __shared__ float2 sW[RNK * DIN];
    __shared__ float  sred[128];
    const float c = 0.5f * DT_F;
    const int t = threadIdx.x;   // 128 threads

    if (t < N) {
        float om = expf(lw[t]);
        float ze = 1.f / (1.f + expf(-zl[t]));
        float lr = -ze * om;
        float li = om * sqrtf(fmaxf(1.f - ze * ze, 1e-8f));
        float mr = 1.f - c * lr;
        float mi = -c * li;
        float inv = 1.f / (mr * mr + mi * mi);
        sminv[t] = make_float2(mr * inv, -mi * inv);
    }
    __syncthreads();

    // S = c * Q^T Minv P  (4x4 complex)
    if (t < 16) {
        int r = t >> 2, s2 = t & 3;
        float2 acc = make_float2(0.f, 0.f);
        for (int k = 0; k < N; k++) {
            float coef = Q[k * RNK + r] * P[k * RNK + s2];
            acc.x += coef * sminv[k].x;
            acc.y += coef * sminv[k].y;
        }
        sS[t] = make_float2(c * acc.x, c * acc.y);
    }
    __syncthreads();

    // K = inv(I4 - S), Gauss-Jordan
    if (t == 0) {
        float2 M_[4][8];
        for (int i = 0; i < 4; i++)
            for (int j = 0; j < 4; j++) {
                float2 v = sS[i * 4 + j];
                M_[i][j] = make_float2((i == j ? 1.f : 0.f) - v.x, -v.y);
                M_[i][4 + j] = make_float2(i == j ? 1.f : 0.f, 0.f);
            }
        for (int col = 0; col < 4; col++) {
            float2 p = M_[col][col];
            float d = 1.f / (p.x * p.x + p.y * p.y);
            float2 pinv = make_float2(p.x * d, -p.y * d);
            for (int j = 0; j < 8; j++) M_[col][j] = cmulf(M_[col][j], pinv);
            for (int rr = 0; rr < 4; rr++)
                if (rr != col) {
                    float2 f = M_[rr][col];
                    for (int j = 0; j < 8; j++) {
                        float2 s = cmulf(f, M_[col][j]);
                        M_[rr][j].x -= s.x;
                        M_[rr][j].y -= s.y;
                    }
                }
        }
        for (int i = 0; i < 4; i++)
            for (int j = 0; j < 4; j++) sK[i * 4 + j] = M_[i][4 + j];
    }
    __syncthreads();

    // Da, U, V
    if (t < N) {
        float2 mv = sminv[t];
        g_Da[t] = make_float2(2.f * mv.x - 1.f, 2.f * mv.y);
        #pragma unroll
        for (int r = 0; r < RNK; r++) {
            float2 pk = make_float2(0.f, 0.f);
            #pragma unroll
            for (int s2 = 0; s2 < RNK; s2++) {
                float pv = P[t * RNK + s2];
                pk.x += pv * sK[s2 * 4 + r].x;
                pk.y += pv * sK[s2 * 4 + r].y;
            }
            float2 u = cmulf(make_float2(2.f * c * mv.x, 2.f * c * mv.y), pk);
            g_U[t * RNK + r] = u;
            float qv = Q[t * RNK + r];
            g_V[r * N + t] = make_float2(qv * mv.x, qv * mv.y);
        }
    }
    __syncthreads();

    // W[r][i] = sum_k V[r][k] * B[k][i]
    {
        int i = t;
        #pragma unroll
        for (int r = 0; r < RNK; r++) {
            float2 acc = make_float2(0.f, 0.f);
            for (int k = 0; k < N; k++) {
                float coef = Q[k * RNK + r] * Bm[k * DIN + i];
                acc.x += coef * sminv[k].x;
                acc.y += coef * sminv[k].y;
            }
            sW[r * DIN + i] = acc;
        }
    }
    __syncthreads();

    const float sq = sqrtf(DT_F);
    // g_Wf: [k][2r+c]
    #pragma unroll
    for (int r = 0; r < RNK; r++) {
        g_Wf[t * 8 + 2 * r]     = sW[r * DIN + t].x;
        g_Wf[t * 8 + 2 * r + 1] = sW[r * DIN + t].y;
    }
    // g_Br: [i][n] = B[n][i]
    for (int idx = t; idx < DIN * 64; idx += 128) {
        int i = idx >> 6, n = idx & 63;
        g_Br[i * 64 + n] = Bm[n * DIN + i];
    }
    // g_epi: me = sq*minv (scan folds the rank term via U directly)
    if (t < N) {
        float2 mv = sminv[t];
        g_epi[t * 10 + 0] = sq * mv.x;
        g_epi[t * 10 + 1] = sq * mv.y;
    }
    // dense A_d
    for (int idx = t; idx < N * N; idx += 128) {
        int j = idx >> 6, k = idx & 63;
        float2 acc = (j == k) ? g_Da[j] : make_float2(0.f, 0.f);
        #pragma unroll
        for (int r = 0; r < RNK; r++) acc = cfma(g_U[j * RNK + r], g_V[r * N + k], acc);
        g_Ad[j * N + k] = acc;
    }
    // transposes
    for (int idx = t; idx < DOUT * N; idx += 128) {
        int o = idx & 127, k = idx >> 7;
        g_CT[k * DOUT + o] = C[o * N + k];
    }
    for (int idx = t; idx < DOUT * DIN; idx += 128) {
        int o = idx & 127, k = idx >> 7;
        g_DT[k * DOUT + o] = D[o * DIN + k];
    }
    // D-zero flag
    {
        float s = 0.f;
        for (int i = t; i < DOUT * DIN; i += 128) s += fabsf(D[i]);
        sred[t] = s;
        __syncthreads();
        for (int st = 64; st > 0; st >>= 1) {
            if (t < st) sred[t] += sred[t + st];
            __syncthreads();
        }
        if (t == 0) g_dflag = (sred[0] != 0.f) ? 1 : 0;
    }
}

// ---------------- A^2 squaring with 4-way k-split ILP (64x64 complex) ----------------
// grid=64 (one row per block), block=256: thread (col = t&63, part = t>>6) sums 16 k's.
__global__ __launch_bounds__(256) void sqmat_kernel(int srcSel) {
    const float2* src = srcSel ? g_Atmp : g_Ad;
    float2*       dst = srcSel ? g_Ad : g_Atmp;
    __shared__ float2 srow[N];
    __shared__ float2 spart[4][64];
    const int row = blockIdx.x, t = threadIdx.x;
    const int col = t & 63, part = t >> 6;
    if (t < 64) srow[t] = src[row * N + t];
    __syncthreads();
    const int k0 = part * 16;
    float2 a0 = make_float2(0.f, 0.f), a1 = a0;
    #pragma unroll
    for (int k = 0; k < 16; k += 2) {
        a0 = cfma(srow[k0 + k],     src[(k0 + k) * N + col],     a0);
        a1 = cfma(srow[k0 + k + 1], src[(k0 + k + 1) * N + col], a1);
    }
    spart[part][col] = make_float2(a0.x + a1.x, a0.y + a1.y);
    __syncthreads();
    if (part == 0) {
        float2 r0 = spart[0][col], r1 = spart[1][col];
        float2 r2 = spart[2][col], r3 = spart[3][col];
        dst[row * N + col] = make_float2((r0.x + r1.x) + (r2.x + r3.x),
                                         (r0.y + r1.y) + (r2.y + r3.y));
    }
}

// ---------------- bu producer: a = u @ B^T (real, 64 cols) and s = 0.05*(u @ W^T) ---------
__global__ __launch_bounds__(256) void bu_gemm_kernel(const float* __restrict__ u) {
    __shared__ float su[32][129];
    __shared__ float sb[32][68];
    __shared__ float sWf[128][8];
    const int tid = threadIdx.x;
    const int tx = tid & 15, ty = tid >> 4;
    const size_t bt0 = (size_t)blockIdx.x * 128;
    typedef unsigned long long ull;

    // W image (4 KB) once per block
    ((float4*)sWf)[tid] = ((const float4*)g_Wf)[tid];

    const int row2 = ty * 8 + (tx >> 1);   // row this thread computes s for
    const int rr0  = (tx & 1) * 4;         // which 4 of the 8 s-components

    ull acc[8][2];
    #pragma unroll
    for (int i = 0; i < 8; i++) { acc[i][0] = 0ull; acc[i][1] = 0ull; }
    float sacc[4] = {0.f, 0.f, 0.f, 0.f};

    for (int k0 = 0; k0 < DIN; k0 += 32) {
        #pragma unroll
        for (int l = 0; l < 4; l++) {
            int idx = tid + l * 256;
            int row = idx >> 3, k4 = idx & 7;
            float4 v = *(const float4*)&u[(bt0 + row) * DIN + k0 + k4 * 4];
            su[k4 * 4 + 0][row] = v.x;
            su[k4 * 4 + 1][row] = v.y;
            su[k4 * 4 + 2][row] = v.z;
            su[k4 * 4 + 3][row] = v.w;
        }
        #pragma unroll
        for (int l = 0; l < 2; l++) {
            int idx = tid + l * 256;
            int n4 = idx & 15, kk = idx >> 4;
            *(float4*)&sb[kk][n4 * 4] = *(const float4*)&g_Br[(k0 + kk) * 64 + n4 * 4];
        }
        __syncthreads();
        #pragma unroll
        for (int k = 0; k < 32; k++) {
            ull a8[8];
            #pragma unroll
            for (int i = 0; i < 8; i++) {
                float av = su[k][ty * 8 + i];
                a8[i] = pack2(av, av);
            }
            ull b0 = *(const ull*)&sb[k][tx * 4];
            ull b1 = *(const ull*)&sb[k][tx * 4 + 2];
            #pragma unroll
            for (int i = 0; i < 8; i++) {
                acc[i][0] = ffma2(a8[i], b0, acc[i][0]);
                acc[i][1] = ffma2(a8[i], b1, acc[i][1]);
            }
            // rank-4 partials
            float uv = su[k][row2];
            float4 wv = *(const float4*)&sWf[k0 + k][rr0];
            sacc[0] = fmaf(uv, wv.x, sacc[0]);
            sacc[1] = fmaf(uv, wv.y, sacc[1]);
            sacc[2] = fmaf(uv, wv.z, sacc[2]);
            sacc[3] = fmaf(uv, wv.w, sacc[3]);
        }
        __syncthreads();
    }
    // store a (real GEMM result)
    #pragma unroll
    for (int i = 0; i < 8; i++) {
        float2 lo = unpack2(acc[i][0]);
        float2 hi = unpack2(acc[i][1]);
        *(float4*)&g_a[(bt0 + ty * 8 + i) * 64 + tx * 4] =
            make_float4(lo.x, lo.y, hi.x, hi.y);
    }
    // store s scaled by 0.5*sqrt(dt) = 0.05
    *(float4*)&g_s[(bt0 + row2) * 8 + rr0] =
        make_float4(0.05f * sacc[0], 0.05f * sacc[1], 0.05f * sacc[2], 0.05f * sacc[3]);
}

// ---------------- chunked scan with folded rank term ----------------
// x <- Da∘x + U(Vx + s) + me∘a   (s pre-scaled by 0.05; me = sqrt(dt)*minv)
__global__ __launch_bounds__(128) void scan_kernel(int mode) {
    const int w  = blockIdx.x * 4 + (threadIdx.x >> 5);
    const int ln = threadIdx.x & 31;
    const int b = w >> 7;        // / G (G=128)
    const int g = w & 127;       // % G
    const size_t bt0 = (size_t)b * T + (size_t)g * L;
    typedef unsigned long long ull;

    float2 Da0 = g_Da[ln], Da1 = g_Da[ln + 32];
    ull da_r  = pack2(Da0.x, Da1.x);
    ull da_i  = pack2(Da0.y, Da1.y);
    ull da_iN = pack2(-Da0.y, -Da1.y);
    ull me_r  = pack2(g_epi[ln * 10 + 0], g_epi[(ln + 32) * 10 + 0]);
    ull me_i  = pack2(g_epi[ln * 10 + 1], g_epi[(ln + 32) * 10 + 1]);
    ull ur[RNK], ui[RNK], uiN[RNK], vr[RNK], vi[RNK], viN[RNK];
    #pragma unroll
    for (int r = 0; r < RNK; r++) {
        float2 U0 = g_U[ln * RNK + r], U1 = g_U[(ln + 32) * RNK + r];
        float2 V0 = g_V[r * N + ln],   V1 = g_V[r * N + ln + 32];
        ur[r]  = pack2(U0.x, U1.x);
        ui[r]  = pack2(U0.y, U1.y);
        uiN[r] = pack2(-U0.y, -U1.y);
        vr[r]  = pack2(V0.x, V1.x);
        vi[r]  = pack2(V0.y, V1.y);
        viN[r] = pack2(-V0.y, -V1.y);
    }

    ull xr = 0ull, xi = 0ull;
    if (mode) {
        int ci = (b * G + g) * N;
        float2 x0 = g_xin[ci + ln], x1 = g_xin[ci + ln + 32];
        xr = pack2(x0.x, x1.x);
        xi = pack2(x0.y, x1.y);
    }

    const float*  ap = g_a + bt0 * 64;
    const float4* sp = (const float4*)(g_s + bt0 * 8);
    float  ar0[PF], ar1[PF];
    float4 sr0[PF], sr1[PF];
    #pragma unroll
    for (int j = 0; j < PF; j++) {
        ar0[j] = ap[j * 64 + ln];
        ar1[j] = ap[j * 64 + ln + 32];
        sr0[j] = sp[j * 2];
        sr1[j] = sp[j * 2 + 1];
    }

    const ull zero = 0ull;
    #pragma unroll 1
    for (int t0 = 0; t0 < L; t0 += PF) {
        #pragma unroll
        for (int j = 0; j < PF; j++) {
            const int t = t0 + j;
            float av0 = ar0[j], av1 = ar1[j];
            float4 sv0 = sr0[j], sv1 = sr1[j];
            if (t + PF < L) {
                ar0[j] = ap[(t + PF) * 64 + ln];
                ar1[j] = ap[(t + PF) * 64 + ln + 32];
                sr0[j] = sp[(t + PF) * 2];
                sr1[j] = sp[(t + PF) * 2 + 1];
            }
            float sre[RNK], sim[RNK];
            #pragma unroll
            for (int r = 0; r < RNK; r++) {
                ull pr = ffma2(viN[r], xi, ffma2(vr[r], xr, zero));
                ull pi = ffma2(vi[r],  xr, ffma2(vr[r], xi, zero));
                float2 a  = unpack2(pr);
                float2 bb = unpack2(pi);
                sre[r] = a.x + a.y;
                sim[r] = bb.x + bb.y;
            }
            #pragma unroll
            for (int off = 16; off > 0; off >>= 1) {
                #pragma unroll
                for (int r = 0; r < RNK; r++) {
                    sre[r] += __shfl_xor_sync(0xffffffffu, sre[r], off);
                    sim[r] += __shfl_xor_sync(0xffffffffu, sim[r], off);
                }
            }
            // fold the bu rank-4 term: s values are broadcast (same for all lanes)
            sre[0] += sv0.x; sim[0] += sv0.y;
            sre[1] += sv0.z; sim[1] += sv0.w;
            sre[2] += sv1.x; sim[2] += sv1.y;
            sre[3] += sv1.z; sim[3] += sv1.w;

            ull apk = pack2(av0, av1);
            ull yr = ffma2(da_r, xr, ffma2(da_iN, xi, ffma2(me_r, apk, zero)));
            ull yi = ffma2(da_r, xi, ffma2(da_i,  xr, ffma2(me_i, apk, zero)));
            #pragma unroll
            for (int r = 0; r < RNK; r++) {
                ull pr = pack2(sre[r], sre[r]);
                ull pi = pack2(sim[r], sim[r]);
                yr = ffma2(uiN[r], pi, ffma2(ur[r], pr, yr));
                yi = ffma2(ui[r],  pr, ffma2(ur[r], pi, yi));
            }
            xr = yr;
            xi = yi;
            if (mode) {
                float2 o = unpack2(xr);
                g_xr[(bt0 + t) * N + ln]      = o.x;
                g_xr[(bt0 + t) * N + ln + 32] = o.y;
            }
        }
    }
    if (!mode) {
        int ci = (b * G + g) * N;
        float2 rr = unpack2(xr), i2 = unpack2(xi);
        g_csum[ci + ln]      = make_float2(rr.x, i2.x);
        g_csum[ci + ln + 32] = make_float2(rr.y, i2.y);
    }
}

// ---------------- chunk-level chain: x_in[g+1] = A^L x_in[g] + c_g ----------------
__global__ __launch_bounds__(64) void chain_kernel() {
    __shared__ float2 sA[N * 65];
    __shared__ float2 sx[N];
    const int b = blockIdx.x, t = threadIdx.x;
    for (int i = t; i < N * N; i += 64) {
        int r = i >> 6, c = i & 63;
        sA[r * 65 + c] = g_Ad[i];   // A^64 (6 sqmat launches -> result in g_Ad)
    }
    float2 x = make_float2(0.f, 0.f);
    for (int g = 0; g < G; g++) {
        int ci = (b * G + g) * N;
        g_xin[ci + t] = x;
        sx[t] = x;
        __syncthreads();
        float2 a0 = g_csum[ci + t];
        float2 a1 = make_float2(0.f, 0.f), a2 = a1, a3 = a1;
        #pragma unroll 4
        for (int k = 0; k < N; k += 4) {
            a0 = cfma(sA[t * 65 + k + 0], sx[k + 0], a0);
            a1 = cfma(sA[t * 65 + k + 1], sx[k + 1], a1);
            a2 = cfma(sA[t * 65 + k + 2], sx[k + 2], a2);
            a3 = cfma(sA[t * 65 + k + 3], sx[k + 3], a3);
        }
        x.x = (a0.x + a1.x) + (a2.x + a3.x);
        x.y = (a0.y + a1.y) + (a2.y + a3.y);
        __syncthreads();
    }
}

// ---------------- y = Re(x) @ C^T (+ u @ D^T if D != 0), packed f32x2 GEMM (R3) ----------
__global__ __launch_bounds__(256) void y_gemm_kernel(const float* __restrict__ u,
                                                     float* __restrict__ out) {
    __shared__ float sx[32][129];
    __shared__ float sc[32][132];
    const int tid = threadIdx.x;
    const int tx = tid & 15, ty = tid >> 4;
    const size_t bt0 = (size_t)blockIdx.x * 128;

    unsigned long long acc[8][4];
    #pragma unroll
    for (int i = 0; i < 8; i++)
        #pragma unroll
        for (int j = 0; j < 4; j++) acc[i][j] = 0ull;

    for (int k0 = 0; k0 < N; k0 += 32) {
        #pragma unroll
        for (int l = 0; l < 4; l++) {
            int idx = tid + l * 256;
            int row = idx >> 3, k4 = idx & 7;
            float4 v = *(const float4*)&g_xr[(bt0 + row) * N + k0 + k4 * 4];
            sx[k4 * 4 + 0][row] = v.x;
            sx[k4 * 4 + 1][row] = v.y;
            sx[k4 * 4 + 2][row] = v.z;
            sx[k4 * 4 + 3][row] = v.w;
        }
        #pragma unroll
        for (int l = 0; l < 4; l++) {
            int idx = tid + l * 256;
            int o4 = idx & 31, kk = idx >> 5;
            float4 v = *(const float4*)&g_CT[(k0 + kk) * DOUT + o4 * 4];
            *(float4*)&sc[kk][o4 * 4] = v;
        }
        __syncthreads();
        #pragma unroll
        for (int k = 0; k < 32; k++) {
            unsigned long long a8[8], b4[4];
            #pragma unroll
            for (int i = 0; i < 8; i++) {
                float av = sx[k][ty * 8 + i];
                a8[i] = pack2(av, av);
            }
            #pragma unroll
            for (int j = 0; j < 4; j++)
                b4[j] = *(const unsigned long long*)&sc[k][tx * 8 + 2 * j];
            #pragma unroll
            for (int i = 0; i < 8; i++)
                #pragma unroll
                for (int j = 0; j < 4; j++) acc[i][j] = ffma2(a8[i], b4[j], acc[i][j]);
        }
        __syncthreads();
    }
    if (g_dflag) {
        for (int k0 = 0; k0 < DIN; k0 += 32) {
            #pragma unroll
            for (int l = 0; l < 4; l++) {
                int idx = tid + l * 256;
                int row = idx >> 3, k4 = idx & 7;
                float4 v = *(const float4*)&u[(bt0 + row) * DIN + k0 + k4 * 4];
                sx[k4 * 4 + 0][row] = v.x;
                sx[k4 * 4 + 1][row] = v.y;
                sx[k4 * 4 + 2][row] = v.z;
                sx[k4 * 4 + 3][row] = v.w;
            }
            #pragma unroll
            for (int l = 0; l < 4; l++) {
                int idx = tid + l * 256;
                int o4 = idx & 31, kk = idx >> 5;
                float4 v = *(const float4*)&g_DT[(k0 + kk) * DOUT + o4 * 4];
                *(float4*)&sc[kk][o4 * 4] = v;
            }
            __syncthreads();
            #pragma unroll
            for (int k = 0; k < 32; k++) {
                unsigned long long a8[8], b4[4];
                #pragma unroll
                for (int i = 0; i < 8; i++) {
                    float av = sx[k][ty * 8 + i];
                    a8[i] = pack2(av, av);
                }
                #pragma unroll
                for (int j = 0; j < 4; j++)
                    b4[j] = *(const unsigned long long*)&sc[k][tx * 8 + 2 * j];
                #pragma unroll
                for (int i = 0; i < 8; i++)
                    #pragma unroll
                    for (int j = 0; j < 4; j++) acc[i][j] = ffma2(a8[i], b4[j], acc[i][j]);
            }
            __syncthreads();
        }
    }
    #pragma unroll
    for (int i = 0; i < 8; i++) {
        float2 p0 = unpack2(acc[i][0]);
        float2 p1 = unpack2(acc[i][1]);
        float2 p2 = unpack2(acc[i][2]);
        float2 p3 = unpack2(acc[i][3]);
        float4 v0 = make_float4(p0.x, p0.y, p1.x, p1.y);
        float4 v1 = make_float4(p2.x, p2.y, p3.x, p3.y);
        size_t base = (bt0 + ty * 8 + i) * DOUT + tx * 8;
        *(float4*)&out[base]     = v0;
        *(float4*)&out[base + 4] = v1;
    }
}

// ---------------- launch (scan0 at index 3: ncu -s 5 with 2 hidden launches profiles it) --
extern "C" void kernel_launch(void* const* d_in, const int* in_sizes, int n_in,
                              void* d_out, int out_size) {
    const float* u  = (const float*)d_in[0];
    const float* lw = (const float*)d_in[1];
    const float* zl = (const float*)d_in[2];
    const float* P  = (const float*)d_in[3];
    const float* Q  = (const float*)d_in[4];
    const float* Bm = (const float*)d_in[5];
    const float* C  = (const float*)d_in[6];
    const float* D  = (const float*)d_in[7];
    float* out = (float*)d_out;

    setup_kernel<<<1, 128>>>(lw, zl, P, Q, Bm, C, D);   // 0
    bu_gemm_kernel<<<BT / 128, 256>>>(u);               // 1
    sqmat_kernel<<<N, 256>>>(0);                        // 2  A^2  -> Atmp
    scan_kernel<<<(BATCH * G) / 4, 128>>>(0);           // 3  <- ncu-profiled launch
    sqmat_kernel<<<N, 256>>>(1);                        // 4  A^4  -> Ad
    sqmat_kernel<<<N, 256>>>(0);                        // 5  A^8  -> Atmp
    sqmat_kernel<<<N, 256>>>(1);                        // 6  A^16 -> Ad
    sqmat_kernel<<<N, 256>>>(0);                        // 7  A^32 -> Atmp
    sqmat_kernel<<<N, 256>>>(1);                        // 8  A^64 -> Ad
    chain_kernel<<<BATCH, 64>>>();                      // 9
    scan_kernel<<<(BATCH * G) / 4, 128>>>(1);           // 10
    y_gemm_kernel<<<BT / 128, 256>>>(u, out);           // 11
}